// round 7
// baseline (speedup 1.0000x reference)
#include <cuda_runtime.h>
#include <cuda_fp16.h>

#define N_NODES 50000
#define N_EDGES 1600000
#define E_TOT   (N_EDGES + N_NODES)
#define IN_C    256
#define HID_C   128
#define OUT_C   16
#define HEADS   8
#define NBLK_SCAN 49   // ceil(50000/1024)

// ---------------- scratch (device globals; no allocation allowed) ------------
__device__ __align__(256) __half g_h1h[N_NODES * HID_C];     // fp16 messages L1
__device__ __align__(256) float  g_asrc1[N_NODES * HEADS];
__device__ __align__(256) float  g_adst1[N_NODES * HEADS];
__device__ __align__(256) __half g_hreluh[N_NODES * HID_C];  // fp16 layer1 out
__device__ __align__(256) __half g_h2h[N_NODES * OUT_C];     // fp16 messages L2
__device__ __align__(256) float  g_asrc2[N_NODES];
__device__ __align__(256) float  g_adst2[N_NODES];
__device__ __align__(256) int    g_deg[N_NODES];
__device__ __align__(256) int    g_off[N_NODES + 1];
__device__ __align__(256) int    g_cursor[N_NODES];
__device__ __align__(256) int    g_part[64];
__device__ __align__(256) int    g_csr_src[E_TOT];

__device__ __forceinline__ float lrelu(float a) {
    return a > 0.0f ? a : 0.2f * a;
}

__device__ __forceinline__ unsigned to_tf32(float f) {
    unsigned u;
    asm("cvt.rna.tf32.f32 %0, %1;" : "=r"(u) : "f"(f));
    return u;
}

__device__ __forceinline__ void mma_tf32(float* d, const unsigned* a, const unsigned* b) {
    asm volatile(
        "mma.sync.aligned.m16n8k8.row.col.f32.tf32.tf32.f32 "
        "{%0,%1,%2,%3}, {%4,%5,%6,%7}, {%8,%9}, {%0,%1,%2,%3};\n"
        : "+f"(d[0]), "+f"(d[1]), "+f"(d[2]), "+f"(d[3])
        : "r"(a[0]), "r"(a[1]), "r"(a[2]), "r"(a[3]), "r"(b[0]), "r"(b[1]));
}

// ---------------- CSR build ---------------------------------------------------
__global__ void zero_deg_kernel() {
    int i = blockIdx.x * blockDim.x + threadIdx.x;
    if (i < N_NODES) g_deg[i] = 0;
}

__global__ void count_kernel(const int* __restrict__ dst) {
    int e = blockIdx.x * blockDim.x + threadIdx.x;
    if (e >= E_TOT) return;
    int d = (e < N_EDGES) ? dst[e] : e - N_EDGES;
    atomicAdd(&g_deg[d], 1);
}

__global__ void scanA_kernel() {   // 49 blocks x 256 threads: block partial sums
    __shared__ int sh[8];
    int b = blockIdx.x, t = threadIdx.x;
    int base = b * 1024 + t * 4;
    int s = 0;
#pragma unroll
    for (int k = 0; k < 4; k++) { int i = base + k; if (i < N_NODES) s += g_deg[i]; }
#pragma unroll
    for (int o = 16; o; o >>= 1) s += __shfl_xor_sync(0xffffffffu, s, o);
    if ((t & 31) == 0) sh[t >> 5] = s;
    __syncthreads();
    if (t < 8) {
        int v = sh[t];
#pragma unroll
        for (int o = 4; o; o >>= 1) v += __shfl_xor_sync(0xffffffffu, v, o);
        if (t == 0) g_part[b] = v;
    }
}

__global__ void scanC_kernel() {   // final offsets; scans the 49 partials inline
    __shared__ int ws[8];
    __shared__ int s_pre;
    int b = blockIdx.x, t = threadIdx.x;
    int lane = t & 31, w = t >> 5;
    if (w == 0) {   // warp 0: exclusive prefix of block partials
        int v = 0;
        if (lane < b && lane < NBLK_SCAN) v = g_part[lane];
        if (lane + 32 < b && lane + 32 < NBLK_SCAN) v += g_part[lane + 32];
#pragma unroll
        for (int o = 16; o; o >>= 1) v += __shfl_xor_sync(0xffffffffu, v, o);
        if (lane == 0) s_pre = v;
    }
    int base = b * 1024 + t * 4;
    int d0 = 0, d1 = 0, d2 = 0, d3 = 0;
    if (base + 0 < N_NODES) d0 = g_deg[base + 0];
    if (base + 1 < N_NODES) d1 = g_deg[base + 1];
    if (base + 2 < N_NODES) d2 = g_deg[base + 2];
    if (base + 3 < N_NODES) d3 = g_deg[base + 3];
    int tsum = d0 + d1 + d2 + d3;
    int v = tsum;
#pragma unroll
    for (int o = 1; o < 32; o <<= 1) {
        int u = __shfl_up_sync(0xffffffffu, v, o);
        if (lane >= o) v += u;
    }
    if (lane == 31) ws[w] = v;
    __syncthreads();
    int woff = 0;
    for (int i = 0; i < w; i++) woff += ws[i];
    int excl = v - tsum + woff + s_pre;
    int o0 = excl, o1 = o0 + d0, o2 = o1 + d1, o3 = o2 + d2;
    if (base + 0 < N_NODES) { g_off[base + 0] = o0; g_cursor[base + 0] = o0; }
    if (base + 1 < N_NODES) { g_off[base + 1] = o1; g_cursor[base + 1] = o1; }
    if (base + 2 < N_NODES) { g_off[base + 2] = o2; g_cursor[base + 2] = o2; }
    if (base + 3 < N_NODES) { g_off[base + 3] = o3; g_cursor[base + 3] = o3; }
    if (b == 0 && t == 0) g_off[N_NODES] = E_TOT;
}

__global__ void scatter_kernel(const int* __restrict__ src, const int* __restrict__ dst) {
    int e = blockIdx.x * blockDim.x + threadIdx.x;
    if (e >= E_TOT) return;
    int s, d;
    if (e < N_EDGES) { s = src[e]; d = dst[e]; }
    else             { s = d = e - N_EDGES; }
    int pos = atomicAdd(&g_cursor[d], 1);
    g_csr_src[pos] = s;
}

// ---------------- GEMM1 (tf32 MMA) + fused att scores + fp16 h1 --------------
__global__ __launch_bounds__(256) void gemm1_kernel(const float* __restrict__ A,
                                                    const float* __restrict__ B,
                                                    const float* __restrict__ att_s,
                                                    const float* __restrict__ att_d) {
    __shared__ float As[2][2048];
    __shared__ float Bs[2][2048];
    const int M = N_NODES;
    int rowBase = blockIdx.x * 128;
    int tid = threadIdx.x;
    int lane = tid & 31;
    int warpId = tid >> 5;
    int wmRow = (warpId >> 1) * 32;
    int wnCol = (warpId & 1) * 64;

    float acc[2][8][4];
#pragma unroll
    for (int i = 0; i < 2; i++)
#pragma unroll
        for (int j = 0; j < 8; j++)
#pragma unroll
            for (int q = 0; q < 4; q++) acc[i][j][q] = 0.0f;

#pragma unroll
    for (int p = 0; p < 2; p++) {
        int fidx = tid + p * 256;
        int arow = fidx >> 2;
        int kc = (fidx & 3) * 4;
        int gr = rowBase + arow;
        float4 av = make_float4(0.f, 0.f, 0.f, 0.f);
        if (gr < M) av = *(const float4*)&A[(long)gr * IN_C + kc];
        float ae[4] = { av.x, av.y, av.z, av.w };
#pragma unroll
        for (int i = 0; i < 4; i++) {
            int kl = kc + i;
            As[0][(((kl >> 3) * 128 + arow) * 4 + (kl & 3)) * 2 + ((kl >> 2) & 1)] = ae[i];
        }
        int krow = fidx >> 5;
        int n0 = (fidx & 31) * 4;
        float4 bv = *(const float4*)&B[krow * 128 + n0];
        float be[4] = { bv.x, bv.y, bv.z, bv.w };
#pragma unroll
        for (int i = 0; i < 4; i++) {
            Bs[0][(((krow >> 3) * 128 + n0 + i) * 4 + (krow & 3)) * 2 + ((krow >> 2) & 1)] = be[i];
        }
    }
    __syncthreads();

    float4 ra[2], rb[2];
    for (int c = 0; c < 16; c++) {
        int buf = c & 1;
        if (c < 15) {
            int kbase = (c + 1) * 16;
#pragma unroll
            for (int p = 0; p < 2; p++) {
                int fidx = tid + p * 256;
                int arow = fidx >> 2;
                int kc = (fidx & 3) * 4;
                int gr = rowBase + arow;
                ra[p] = make_float4(0.f, 0.f, 0.f, 0.f);
                if (gr < M) ra[p] = *(const float4*)&A[(long)gr * IN_C + kbase + kc];
                int krow = fidx >> 5;
                int n0 = (fidx & 31) * 4;
                rb[p] = *(const float4*)&B[(kbase + krow) * 128 + n0];
            }
        }
        const float2* As2 = (const float2*)As[buf];
        const float2* Bs2 = (const float2*)Bs[buf];
#pragma unroll
        for (int s = 0; s < 2; s++) {
            unsigned ua[2][4], ub[8][2];
#pragma unroll
            for (int mi = 0; mi < 2; mi++) {
                int rb_ = wmRow + mi * 16 + (lane >> 2);
                float2 lo = As2[(s * 128 + rb_) * 4 + (lane & 3)];
                float2 hi = As2[(s * 128 + rb_ + 8) * 4 + (lane & 3)];
                ua[mi][0] = to_tf32(lo.x);
                ua[mi][1] = to_tf32(hi.x);
                ua[mi][2] = to_tf32(lo.y);
                ua[mi][3] = to_tf32(hi.y);
            }
#pragma unroll
            for (int nj = 0; nj < 8; nj++) {
                int nb = wnCol + nj * 8 + (lane >> 2);
                float2 bb = Bs2[(s * 128 + nb) * 4 + (lane & 3)];
                ub[nj][0] = to_tf32(bb.x);
                ub[nj][1] = to_tf32(bb.y);
            }
#pragma unroll
            for (int mi = 0; mi < 2; mi++)
#pragma unroll
                for (int nj = 0; nj < 8; nj++)
                    mma_tf32(acc[mi][nj], ua[mi], ub[nj]);
        }
        if (c < 15) {
            int nb_ = buf ^ 1;
#pragma unroll
            for (int p = 0; p < 2; p++) {
                int fidx = tid + p * 256;
                int arow = fidx >> 2;
                int kc = (fidx & 3) * 4;
                float ae[4] = { ra[p].x, ra[p].y, ra[p].z, ra[p].w };
#pragma unroll
                for (int i = 0; i < 4; i++) {
                    int kl = kc + i;
                    As[nb_][(((kl >> 3) * 128 + arow) * 4 + (kl & 3)) * 2 + ((kl >> 2) & 1)] = ae[i];
                }
                int krow = fidx >> 5;
                int n0 = (fidx & 31) * 4;
                float be[4] = { rb[p].x, rb[p].y, rb[p].z, rb[p].w };
#pragma unroll
                for (int i = 0; i < 4; i++) {
                    Bs[nb_][(((krow >> 3) * 128 + n0 + i) * 4 + (krow & 3)) * 2 + ((krow >> 2) & 1)] = be[i];
                }
            }
        }
        __syncthreads();
    }

    // ---- epilogue 1: fp16 h1 stores ----
#pragma unroll
    for (int mi = 0; mi < 2; mi++) {
#pragma unroll
        for (int nj = 0; nj < 8; nj++) {
            int r0 = rowBase + wmRow + mi * 16 + (lane >> 2);
            int col = wnCol + nj * 8 + (lane & 3) * 2;
            if (r0 < M)
                *(__half2*)&g_h1h[r0 * 128 + col] = __floats2half2_rn(acc[mi][nj][0], acc[mi][nj][1]);
            if (r0 + 8 < M)
                *(__half2*)&g_h1h[(r0 + 8) * 128 + col] = __floats2half2_rn(acc[mi][nj][2], acc[mi][nj][3]);
        }
    }

    // ---- epilogue 2: fused attention scores (per-head dots) ----
    float s_part[2][2][4], d_part[2][2][4];
#pragma unroll
    for (int mi = 0; mi < 2; mi++)
#pragma unroll
        for (int r = 0; r < 2; r++)
#pragma unroll
            for (int hh = 0; hh < 4; hh++) { s_part[mi][r][hh] = 0.f; d_part[mi][r][hh] = 0.f; }

#pragma unroll
    for (int mi = 0; mi < 2; mi++) {
#pragma unroll
        for (int nj = 0; nj < 8; nj++) {
            int hh = nj >> 1;
            int ch0 = wnCol + nj * 8 + (lane & 3) * 2;
            float as0 = att_s[ch0], as1 = att_s[ch0 + 1];
            float ad0 = att_d[ch0], ad1 = att_d[ch0 + 1];
            s_part[mi][0][hh] += acc[mi][nj][0] * as0 + acc[mi][nj][1] * as1;
            d_part[mi][0][hh] += acc[mi][nj][0] * ad0 + acc[mi][nj][1] * ad1;
            s_part[mi][1][hh] += acc[mi][nj][2] * as0 + acc[mi][nj][3] * as1;
            d_part[mi][1][hh] += acc[mi][nj][2] * ad0 + acc[mi][nj][3] * ad1;
        }
    }
#pragma unroll
    for (int mi = 0; mi < 2; mi++)
#pragma unroll
        for (int r = 0; r < 2; r++)
#pragma unroll
            for (int hh = 0; hh < 4; hh++) {
                float vs = s_part[mi][r][hh], vd = d_part[mi][r][hh];
                vs += __shfl_xor_sync(0xffffffffu, vs, 1);
                vs += __shfl_xor_sync(0xffffffffu, vs, 2);
                vd += __shfl_xor_sync(0xffffffffu, vd, 1);
                vd += __shfl_xor_sync(0xffffffffu, vd, 2);
                s_part[mi][r][hh] = vs;
                d_part[mi][r][hh] = vd;
            }
    if ((lane & 3) == 0) {
        int hbase = wnCol >> 4;
#pragma unroll
        for (int mi = 0; mi < 2; mi++) {
            int r0 = rowBase + wmRow + mi * 16 + (lane >> 2);
#pragma unroll
            for (int r = 0; r < 2; r++) {
                int row = r0 + r * 8;
                if (row < M) {
#pragma unroll
                    for (int hh = 0; hh < 4; hh++) {
                        g_asrc1[row * 8 + hbase + hh] = s_part[mi][r][hh];
                        g_adst1[row * 8 + hbase + hh] = d_part[mi][r][hh];
                    }
                }
            }
        }
    }
}

// ---------------- layer1 gather: warp per node, 4 edges in flight ------------
// lane = g*8 + l : group g (edge j+g), lane-l owns head l (16 channels).
__global__ __launch_bounds__(256) void gather1_kernel(const float* __restrict__ bias) {
    int n = (blockIdx.x * blockDim.x + threadIdx.x) >> 5;
    int lane = threadIdx.x & 31;
    if (n >= N_NODES) return;
    int g = lane >> 3, l = lane & 7;
    float adv = g_adst1[n * 8 + l];
    int jbeg = g_off[n], jend = g_off[n + 1];
    float acc[16];
#pragma unroll
    for (int k = 0; k < 16; k++) acc[k] = 0.0f;
    float dsum = 0.0f;
    const __half* h1base = g_h1h;
#pragma unroll 2
    for (int j = jbeg; j < jend; j += 4) {
        int jj = j + g;
        bool valid = jj < jend;
        int sa = g_csr_src[valid ? jj : jbeg];
        float ea = __expf(lrelu(g_asrc1[sa * 8 + l] + adv));
        if (!valid) ea = 0.0f;
        const uint4* hp = (const uint4*)&h1base[sa * 128 + l * 16];
        uint4 r0 = hp[0];
        uint4 r1 = hp[1];
        const __half2* p0 = (const __half2*)&r0;
        const __half2* p1 = (const __half2*)&r1;
#pragma unroll
        for (int q = 0; q < 4; q++) {
            float2 f0 = __half22float2(p0[q]);
            float2 f1 = __half22float2(p1[q]);
            acc[q * 2 + 0] += f0.x * ea;
            acc[q * 2 + 1] += f0.y * ea;
            acc[8 + q * 2 + 0] += f1.x * ea;
            acc[8 + q * 2 + 1] += f1.y * ea;
        }
        dsum += ea;
    }
    // reduce across the 4 groups (strides 8, 16)
#pragma unroll
    for (int s = 8; s <= 16; s <<= 1) {
        dsum += __shfl_xor_sync(0xffffffffu, dsum, s);
#pragma unroll
        for (int k = 0; k < 16; k++)
            acc[k] += __shfl_xor_sync(0xffffffffu, acc[k], s);
    }
    if (g == 0) {
        float inv = 1.0f / dsum;
        unsigned ov[8];
#pragma unroll
        for (int q = 0; q < 8; q++) {
            float v0 = fmaxf(acc[q * 2 + 0] * inv + bias[l * 16 + q * 2 + 0], 0.0f);
            float v1 = fmaxf(acc[q * 2 + 1] * inv + bias[l * 16 + q * 2 + 1], 0.0f);
            __half2 h = __floats2half2_rn(v0, v1);
            ov[q] = *(unsigned*)&h;
        }
        uint4* op = (uint4*)&g_hreluh[n * 128 + l * 16];
        op[0] = make_uint4(ov[0], ov[1], ov[2], ov[3]);
        op[1] = make_uint4(ov[4], ov[5], ov[6], ov[7]);
    }
}

// ---------------- GEMM2 (+ fused a_src2/a_dst2): h2 = hrelu @ W2 -------------
__global__ __launch_bounds__(256) void gemm2_kernel(const float* __restrict__ W2,
                                                    const float* __restrict__ att_s,
                                                    const float* __restrict__ att_d) {
    __shared__ float Ws[128 * 16];
    __shared__ float Hs[16][128];
    int tid = threadIdx.x;
    int base = blockIdx.x * 16;
    for (int i = tid; i < 128 * 16; i += 256) Ws[i] = W2[i];
    for (int i = tid; i < 16 * 128; i += 256) {
        int r = i >> 7, c = i & 127;
        int gr = base + r;
        Hs[r][c] = (gr < N_NODES) ? __half2float(g_hreluh[gr * 128 + c]) : 0.0f;
    }
    __syncthreads();
    int ty = tid >> 4, tx = tid & 15;
    float sum = 0.0f;
#pragma unroll 8
    for (int k = 0; k < 128; k++) sum += Hs[ty][k] * Ws[k * 16 + tx];
    float ss = sum * att_s[tx];
    float sd = sum * att_d[tx];
#pragma unroll
    for (int off = 8; off; off >>= 1) {
        ss += __shfl_xor_sync(0xffffffffu, ss, off);
        sd += __shfl_xor_sync(0xffffffffu, sd, off);
    }
    int row = base + ty;
    if (row < N_NODES) {
        g_h2h[row * 16 + tx] = __float2half_rn(sum);
        if (tx == 0) { g_asrc2[row] = ss; g_adst2[row] = sd; }
    }
}

// ---------------- layer2 gather: warp per node, 16 edges in flight -----------
// lane = g*2 + l : group g (edge j+g), lane-l owns channels l*8..l*8+7.
__global__ __launch_bounds__(256) void gather2_kernel(const float* __restrict__ bias,
                                                      float* __restrict__ out) {
    int n = (blockIdx.x * blockDim.x + threadIdx.x) >> 5;
    int lane = threadIdx.x & 31;
    if (n >= N_NODES) return;
    int g = lane >> 1, l = lane & 1;
    float adv = g_adst2[n];
    int jbeg = g_off[n], jend = g_off[n + 1];
    float acc[8];
#pragma unroll
    for (int k = 0; k < 8; k++) acc[k] = 0.0f;
    float dsum = 0.0f;
#pragma unroll 2
    for (int j = jbeg; j < jend; j += 16) {
        int jj = j + g;
        bool valid = jj < jend;
        int sa = g_csr_src[valid ? jj : jbeg];
        float ea = __expf(lrelu(g_asrc2[sa] + adv));
        if (!valid) ea = 0.0f;
        uint4 rw = *(const uint4*)&g_h2h[sa * 16 + l * 8];
        const __half2* p = (const __half2*)&rw;
#pragma unroll
        for (int q = 0; q < 4; q++) {
            float2 f = __half22float2(p[q]);
            acc[q * 2 + 0] += f.x * ea;
            acc[q * 2 + 1] += f.y * ea;
        }
        dsum += ea;
    }
    // reduce across the 16 groups (strides 2, 4, 8, 16)
#pragma unroll
    for (int s = 2; s <= 16; s <<= 1) {
        dsum += __shfl_xor_sync(0xffffffffu, dsum, s);
#pragma unroll
        for (int k = 0; k < 8; k++)
            acc[k] += __shfl_xor_sync(0xffffffffu, acc[k], s);
    }
    if (lane < 2) {
        float inv = 1.0f / dsum;
        float4 v0, v1;
        v0.x = acc[0] * inv + bias[l * 8 + 0];
        v0.y = acc[1] * inv + bias[l * 8 + 1];
        v0.z = acc[2] * inv + bias[l * 8 + 2];
        v0.w = acc[3] * inv + bias[l * 8 + 3];
        v1.x = acc[4] * inv + bias[l * 8 + 4];
        v1.y = acc[5] * inv + bias[l * 8 + 5];
        v1.z = acc[6] * inv + bias[l * 8 + 6];
        v1.w = acc[7] * inv + bias[l * 8 + 7];
        *(float4*)&out[n * 16 + l * 8 + 0] = v0;
        *(float4*)&out[n * 16 + l * 8 + 4] = v1;
    }
}

// ---------------- launch ------------------------------------------------------
extern "C" void kernel_launch(void* const* d_in, const int* in_sizes, int n_in,
                              void* d_out, int out_size) {
    const float* x      = (const float*)d_in[0];
    const int*   ei     = (const int*)d_in[1];
    const float* W1     = (const float*)d_in[2];
    const float* att_s1 = (const float*)d_in[3];
    const float* att_d1 = (const float*)d_in[4];
    const float* b1     = (const float*)d_in[5];
    const float* W2     = (const float*)d_in[6];
    const float* att_s2 = (const float*)d_in[7];
    const float* att_d2 = (const float*)d_in[8];
    const float* b2     = (const float*)d_in[9];
    float* out = (float*)d_out;
    const int* src = ei;
    const int* dst = ei + N_EDGES;

    // CSR build (by destination)
    zero_deg_kernel<<<(N_NODES + 255) / 256, 256>>>();
    count_kernel<<<(E_TOT + 255) / 256, 256>>>(dst);
    scanA_kernel<<<NBLK_SCAN, 256>>>();
    scanC_kernel<<<NBLK_SCAN, 256>>>();
    scatter_kernel<<<(E_TOT + 255) / 256, 256>>>(src, dst);

    // layer 1
    gemm1_kernel<<<(N_NODES + 127) / 128, 256>>>(x, W1, att_s1, att_d1);
    gather1_kernel<<<(N_NODES * 32 + 255) / 256, 256>>>(b1);

    // layer 2
    gemm2_kernel<<<(N_NODES + 15) / 16, 256>>>(W2, att_s2, att_d2);
    gather2_kernel<<<(N_NODES * 32 + 255) / 256, 256>>>(b2, out);
}

// round 8
// speedup vs baseline: 1.4260x; 1.4260x over previous
#include <cuda_runtime.h>
#include <cuda_fp16.h>

#define N_NODES 50000
#define N_EDGES 1600000
#define E_TOT   (N_EDGES + N_NODES)
#define IN_C    256
#define HID_C   128
#define OUT_C   16
#define HEADS   8
#define NBLK_SCAN 49   // ceil(50000/1024)

// ---------------- scratch (device globals; zero-initialized at load) ---------
__device__ __align__(256) __half g_h1h[N_NODES * HID_C];     // fp16 messages L1
__device__ __align__(256) float  g_asrc1[N_NODES * HEADS];
__device__ __align__(256) float  g_adst1[N_NODES * HEADS];
__device__ __align__(256) __half g_hreluh[N_NODES * HID_C];  // fp16 layer1 out
__device__ __align__(256) __half g_h2h[N_NODES * OUT_C];     // fp16 messages L2
__device__ __align__(256) float  g_asrc2[N_NODES];
__device__ __align__(256) float  g_adst2[N_NODES];
__device__ __align__(256) int    g_deg[N_NODES];   // zeroed at end of scatter
__device__ __align__(256) int    g_off[N_NODES + 1];
__device__ __align__(256) int    g_cursor[N_NODES];
__device__ __align__(256) int    g_part[64];
__device__ __align__(256) int    g_csr_src[E_TOT];

__device__ __forceinline__ float lrelu(float a) {
    return a > 0.0f ? a : 0.2f * a;
}

__device__ __forceinline__ unsigned to_tf32(float f) {
    unsigned u;
    asm("cvt.rna.tf32.f32 %0, %1;" : "=r"(u) : "f"(f));
    return u;
}

__device__ __forceinline__ void mma_tf32(float* d, const unsigned* a, const unsigned* b) {
    asm volatile(
        "mma.sync.aligned.m16n8k8.row.col.f32.tf32.tf32.f32 "
        "{%0,%1,%2,%3}, {%4,%5,%6,%7}, {%8,%9}, {%0,%1,%2,%3};\n"
        : "+f"(d[0]), "+f"(d[1]), "+f"(d[2]), "+f"(d[3])
        : "r"(a[0]), "r"(a[1]), "r"(a[2]), "r"(a[3]), "r"(b[0]), "r"(b[1]));
}

// accumulate 4 fp16 channels (uint2) weighted by e into float4
__device__ __forceinline__ void facc4(float4& acc, uint2 rw, float e) {
    float2 f01 = __half22float2(*(__half2*)&rw.x);
    float2 f23 = __half22float2(*(__half2*)&rw.y);
    acc.x += f01.x * e;
    acc.y += f01.y * e;
    acc.z += f23.x * e;
    acc.w += f23.y * e;
}

// ---------------- CSR build ---------------------------------------------------
__global__ void count_kernel(const int* __restrict__ dst) {
    int e = blockIdx.x * blockDim.x + threadIdx.x;
    if (e >= E_TOT) return;
    int d = (e < N_EDGES) ? dst[e] : e - N_EDGES;
    atomicAdd(&g_deg[d], 1);
}

__global__ void scanA_kernel() {   // 49 blocks x 256 threads: block partial sums
    __shared__ int sh[8];
    int b = blockIdx.x, t = threadIdx.x;
    int base = b * 1024 + t * 4;
    int s = 0;
#pragma unroll
    for (int k = 0; k < 4; k++) { int i = base + k; if (i < N_NODES) s += g_deg[i]; }
#pragma unroll
    for (int o = 16; o; o >>= 1) s += __shfl_xor_sync(0xffffffffu, s, o);
    if ((t & 31) == 0) sh[t >> 5] = s;
    __syncthreads();
    if (t < 8) {
        int v = sh[t];
#pragma unroll
        for (int o = 4; o; o >>= 1) v += __shfl_xor_sync(0xffffffffu, v, o);
        if (t == 0) g_part[b] = v;
    }
}

__global__ void scanC_kernel() {   // final offsets; scans the 49 partials inline
    __shared__ int ws[8];
    __shared__ int s_pre;
    int b = blockIdx.x, t = threadIdx.x;
    int lane = t & 31, w = t >> 5;
    if (w == 0) {   // warp 0: exclusive prefix of block partials
        int v = 0;
        if (lane < b && lane < NBLK_SCAN) v = g_part[lane];
        if (lane + 32 < b && lane + 32 < NBLK_SCAN) v += g_part[lane + 32];
#pragma unroll
        for (int o = 16; o; o >>= 1) v += __shfl_xor_sync(0xffffffffu, v, o);
        if (lane == 0) s_pre = v;
    }
    int base = b * 1024 + t * 4;
    int d0 = 0, d1 = 0, d2 = 0, d3 = 0;
    if (base + 0 < N_NODES) d0 = g_deg[base + 0];
    if (base + 1 < N_NODES) d1 = g_deg[base + 1];
    if (base + 2 < N_NODES) d2 = g_deg[base + 2];
    if (base + 3 < N_NODES) d3 = g_deg[base + 3];
    int tsum = d0 + d1 + d2 + d3;
    int v = tsum;
#pragma unroll
    for (int o = 1; o < 32; o <<= 1) {
        int u = __shfl_up_sync(0xffffffffu, v, o);
        if (lane >= o) v += u;
    }
    if (lane == 31) ws[w] = v;
    __syncthreads();
    int woff = 0;
    for (int i = 0; i < w; i++) woff += ws[i];
    int excl = v - tsum + woff + s_pre;
    int o0 = excl, o1 = o0 + d0, o2 = o1 + d1, o3 = o2 + d2;
    if (base + 0 < N_NODES) { g_off[base + 0] = o0; g_cursor[base + 0] = o0; }
    if (base + 1 < N_NODES) { g_off[base + 1] = o1; g_cursor[base + 1] = o1; }
    if (base + 2 < N_NODES) { g_off[base + 2] = o2; g_cursor[base + 2] = o2; }
    if (base + 3 < N_NODES) { g_off[base + 3] = o3; g_cursor[base + 3] = o3; }
    if (b == 0 && t == 0) g_off[N_NODES] = E_TOT;
}

__global__ void scatter_kernel(const int* __restrict__ src, const int* __restrict__ dst) {
    int e = blockIdx.x * blockDim.x + threadIdx.x;
    if (e < E_TOT) {
        int s, d;
        if (e < N_EDGES) { s = src[e]; d = dst[e]; }
        else             { s = d = e - N_EDGES; }
        int pos = atomicAdd(&g_cursor[d], 1);
        g_csr_src[pos] = s;
    }
    // re-zero degree counters for the next invocation (deg no longer needed)
    if (e < N_NODES) g_deg[e] = 0;
}

// ---------------- GEMM1 (tf32 MMA) + fused att scores + fp16 h1 --------------
__global__ __launch_bounds__(256) void gemm1_kernel(const float* __restrict__ A,
                                                    const float* __restrict__ B,
                                                    const float* __restrict__ att_s,
                                                    const float* __restrict__ att_d) {
    __shared__ float As[2][2048];
    __shared__ float Bs[2][2048];
    const int M = N_NODES;
    int rowBase = blockIdx.x * 128;
    int tid = threadIdx.x;
    int lane = tid & 31;
    int warpId = tid >> 5;
    int wmRow = (warpId >> 1) * 32;
    int wnCol = (warpId & 1) * 64;

    float acc[2][8][4];
#pragma unroll
    for (int i = 0; i < 2; i++)
#pragma unroll
        for (int j = 0; j < 8; j++)
#pragma unroll
            for (int q = 0; q < 4; q++) acc[i][j][q] = 0.0f;

#pragma unroll
    for (int p = 0; p < 2; p++) {
        int fidx = tid + p * 256;
        int arow = fidx >> 2;
        int kc = (fidx & 3) * 4;
        int gr = rowBase + arow;
        float4 av = make_float4(0.f, 0.f, 0.f, 0.f);
        if (gr < M) av = *(const float4*)&A[(long)gr * IN_C + kc];
        float ae[4] = { av.x, av.y, av.z, av.w };
#pragma unroll
        for (int i = 0; i < 4; i++) {
            int kl = kc + i;
            As[0][(((kl >> 3) * 128 + arow) * 4 + (kl & 3)) * 2 + ((kl >> 2) & 1)] = ae[i];
        }
        int krow = fidx >> 5;
        int n0 = (fidx & 31) * 4;
        float4 bv = *(const float4*)&B[krow * 128 + n0];
        float be[4] = { bv.x, bv.y, bv.z, bv.w };
#pragma unroll
        for (int i = 0; i < 4; i++) {
            Bs[0][(((krow >> 3) * 128 + n0 + i) * 4 + (krow & 3)) * 2 + ((krow >> 2) & 1)] = be[i];
        }
    }
    __syncthreads();

    float4 ra[2], rb[2];
    for (int c = 0; c < 16; c++) {
        int buf = c & 1;
        if (c < 15) {
            int kbase = (c + 1) * 16;
#pragma unroll
            for (int p = 0; p < 2; p++) {
                int fidx = tid + p * 256;
                int arow = fidx >> 2;
                int kc = (fidx & 3) * 4;
                int gr = rowBase + arow;
                ra[p] = make_float4(0.f, 0.f, 0.f, 0.f);
                if (gr < M) ra[p] = *(const float4*)&A[(long)gr * IN_C + kbase + kc];
                int krow = fidx >> 5;
                int n0 = (fidx & 31) * 4;
                rb[p] = *(const float4*)&B[(kbase + krow) * 128 + n0];
            }
        }
        const float2* As2 = (const float2*)As[buf];
        const float2* Bs2 = (const float2*)Bs[buf];
#pragma unroll
        for (int s = 0; s < 2; s++) {
            unsigned ua[2][4], ub[8][2];
#pragma unroll
            for (int mi = 0; mi < 2; mi++) {
                int rb_ = wmRow + mi * 16 + (lane >> 2);
                float2 lo = As2[(s * 128 + rb_) * 4 + (lane & 3)];
                float2 hi = As2[(s * 128 + rb_ + 8) * 4 + (lane & 3)];
                ua[mi][0] = to_tf32(lo.x);
                ua[mi][1] = to_tf32(hi.x);
                ua[mi][2] = to_tf32(lo.y);
                ua[mi][3] = to_tf32(hi.y);
            }
#pragma unroll
            for (int nj = 0; nj < 8; nj++) {
                int nb = wnCol + nj * 8 + (lane >> 2);
                float2 bb = Bs2[(s * 128 + nb) * 4 + (lane & 3)];
                ub[nj][0] = to_tf32(bb.x);
                ub[nj][1] = to_tf32(bb.y);
            }
#pragma unroll
            for (int mi = 0; mi < 2; mi++)
#pragma unroll
                for (int nj = 0; nj < 8; nj++)
                    mma_tf32(acc[mi][nj], ua[mi], ub[nj]);
        }
        if (c < 15) {
            int nb_ = buf ^ 1;
#pragma unroll
            for (int p = 0; p < 2; p++) {
                int fidx = tid + p * 256;
                int arow = fidx >> 2;
                int kc = (fidx & 3) * 4;
                float ae[4] = { ra[p].x, ra[p].y, ra[p].z, ra[p].w };
#pragma unroll
                for (int i = 0; i < 4; i++) {
                    int kl = kc + i;
                    As[nb_][(((kl >> 3) * 128 + arow) * 4 + (kl & 3)) * 2 + ((kl >> 2) & 1)] = ae[i];
                }
                int krow = fidx >> 5;
                int n0 = (fidx & 31) * 4;
                float be[4] = { rb[p].x, rb[p].y, rb[p].z, rb[p].w };
#pragma unroll
                for (int i = 0; i < 4; i++) {
                    Bs[nb_][(((krow >> 3) * 128 + n0 + i) * 4 + (krow & 3)) * 2 + ((krow >> 2) & 1)] = be[i];
                }
            }
        }
        __syncthreads();
    }

    // ---- epilogue 1: fp16 h1 stores ----
#pragma unroll
    for (int mi = 0; mi < 2; mi++) {
#pragma unroll
        for (int nj = 0; nj < 8; nj++) {
            int r0 = rowBase + wmRow + mi * 16 + (lane >> 2);
            int col = wnCol + nj * 8 + (lane & 3) * 2;
            if (r0 < M)
                *(__half2*)&g_h1h[r0 * 128 + col] = __floats2half2_rn(acc[mi][nj][0], acc[mi][nj][1]);
            if (r0 + 8 < M)
                *(__half2*)&g_h1h[(r0 + 8) * 128 + col] = __floats2half2_rn(acc[mi][nj][2], acc[mi][nj][3]);
        }
    }

    // ---- epilogue 2: fused attention scores (per-head dots) ----
    float s_part[2][2][4], d_part[2][2][4];
#pragma unroll
    for (int mi = 0; mi < 2; mi++)
#pragma unroll
        for (int r = 0; r < 2; r++)
#pragma unroll
            for (int hh = 0; hh < 4; hh++) { s_part[mi][r][hh] = 0.f; d_part[mi][r][hh] = 0.f; }

#pragma unroll
    for (int mi = 0; mi < 2; mi++) {
#pragma unroll
        for (int nj = 0; nj < 8; nj++) {
            int hh = nj >> 1;
            int ch0 = wnCol + nj * 8 + (lane & 3) * 2;
            float as0 = att_s[ch0], as1 = att_s[ch0 + 1];
            float ad0 = att_d[ch0], ad1 = att_d[ch0 + 1];
            s_part[mi][0][hh] += acc[mi][nj][0] * as0 + acc[mi][nj][1] * as1;
            d_part[mi][0][hh] += acc[mi][nj][0] * ad0 + acc[mi][nj][1] * ad1;
            s_part[mi][1][hh] += acc[mi][nj][2] * as0 + acc[mi][nj][3] * as1;
            d_part[mi][1][hh] += acc[mi][nj][2] * ad0 + acc[mi][nj][3] * ad1;
        }
    }
#pragma unroll
    for (int mi = 0; mi < 2; mi++)
#pragma unroll
        for (int r = 0; r < 2; r++)
#pragma unroll
            for (int hh = 0; hh < 4; hh++) {
                float vs = s_part[mi][r][hh], vd = d_part[mi][r][hh];
                vs += __shfl_xor_sync(0xffffffffu, vs, 1);
                vs += __shfl_xor_sync(0xffffffffu, vs, 2);
                vd += __shfl_xor_sync(0xffffffffu, vd, 1);
                vd += __shfl_xor_sync(0xffffffffu, vd, 2);
                s_part[mi][r][hh] = vs;
                d_part[mi][r][hh] = vd;
            }
    if ((lane & 3) == 0) {
        int hbase = wnCol >> 4;
#pragma unroll
        for (int mi = 0; mi < 2; mi++) {
            int r0 = rowBase + wmRow + mi * 16 + (lane >> 2);
#pragma unroll
            for (int r = 0; r < 2; r++) {
                int row = r0 + r * 8;
                if (row < M) {
#pragma unroll
                    for (int hh = 0; hh < 4; hh++) {
                        g_asrc1[row * 8 + hbase + hh] = s_part[mi][r][hh];
                        g_adst1[row * 8 + hbase + hh] = d_part[mi][r][hh];
                    }
                }
            }
        }
    }
}

// ---------------- layer1 gather: warp per node, 4-edge index batching --------
// lane l -> channels 4l..4l+3, head l>>2 (same as R4 layout; float4 acc).
__global__ __launch_bounds__(256) void gather1_kernel(const float* __restrict__ bias) {
    int n = (blockIdx.x * blockDim.x + threadIdx.x) >> 5;
    int lane = threadIdx.x & 31;
    if (n >= N_NODES) return;
    int h = lane >> 2;
    float adv = g_adst1[n * 8 + h];
    int j = g_off[n], jend = g_off[n + 1];
    float4 acc = make_float4(0.f, 0.f, 0.f, 0.f);
    float dsum = 0.0f;
    for (; j + 3 < jend; j += 4) {
        // batch 4 indices -> 4 independent asrc + 4 independent h loads in flight
        int s0 = g_csr_src[j];
        int s1 = g_csr_src[j + 1];
        int s2 = g_csr_src[j + 2];
        int s3 = g_csr_src[j + 3];
        float a0 = g_asrc1[s0 * 8 + h];
        float a1 = g_asrc1[s1 * 8 + h];
        float a2 = g_asrc1[s2 * 8 + h];
        float a3 = g_asrc1[s3 * 8 + h];
        uint2 r0 = *(const uint2*)&g_h1h[s0 * 128 + lane * 4];
        uint2 r1 = *(const uint2*)&g_h1h[s1 * 128 + lane * 4];
        uint2 r2 = *(const uint2*)&g_h1h[s2 * 128 + lane * 4];
        uint2 r3 = *(const uint2*)&g_h1h[s3 * 128 + lane * 4];
        float e0 = __expf(lrelu(a0 + adv));
        float e1 = __expf(lrelu(a1 + adv));
        float e2 = __expf(lrelu(a2 + adv));
        float e3 = __expf(lrelu(a3 + adv));
        facc4(acc, r0, e0);
        facc4(acc, r1, e1);
        facc4(acc, r2, e2);
        facc4(acc, r3, e3);
        dsum += (e0 + e1) + (e2 + e3);
    }
    for (; j < jend; j++) {
        int sa = g_csr_src[j];
        float ea = __expf(lrelu(g_asrc1[sa * 8 + h] + adv));
        uint2 rw = *(const uint2*)&g_h1h[sa * 128 + lane * 4];
        facc4(acc, rw, ea);
        dsum += ea;
    }
    float inv = 1.0f / dsum;
    float4 b = *(const float4*)&bias[lane * 4];
    __half2 o01 = __floats2half2_rn(fmaxf(acc.x * inv + b.x, 0.0f),
                                    fmaxf(acc.y * inv + b.y, 0.0f));
    __half2 o23 = __floats2half2_rn(fmaxf(acc.z * inv + b.z, 0.0f),
                                    fmaxf(acc.w * inv + b.w, 0.0f));
    uint2 ov;
    ov.x = *(unsigned*)&o01;
    ov.y = *(unsigned*)&o23;
    *(uint2*)&g_hreluh[n * 128 + lane * 4] = ov;
}

// ---------------- GEMM2 (+ fused a_src2/a_dst2): h2 = hrelu @ W2 -------------
__global__ __launch_bounds__(256) void gemm2_kernel(const float* __restrict__ W2,
                                                    const float* __restrict__ att_s,
                                                    const float* __restrict__ att_d) {
    __shared__ float Ws[128 * 16];
    __shared__ float Hs[16][128];
    int tid = threadIdx.x;
    int base = blockIdx.x * 16;
    for (int i = tid; i < 128 * 16; i += 256) Ws[i] = W2[i];
    for (int i = tid; i < 16 * 128; i += 256) {
        int r = i >> 7, c = i & 127;
        int gr = base + r;
        Hs[r][c] = (gr < N_NODES) ? __half2float(g_hreluh[gr * 128 + c]) : 0.0f;
    }
    __syncthreads();
    int ty = tid >> 4, tx = tid & 15;
    float sum = 0.0f;
#pragma unroll 8
    for (int k = 0; k < 128; k++) sum += Hs[ty][k] * Ws[k * 16 + tx];
    float ss = sum * att_s[tx];
    float sd = sum * att_d[tx];
#pragma unroll
    for (int off = 8; off; off >>= 1) {
        ss += __shfl_xor_sync(0xffffffffu, ss, off);
        sd += __shfl_xor_sync(0xffffffffu, sd, off);
    }
    int row = base + ty;
    if (row < N_NODES) {
        g_h2h[row * 16 + tx] = __float2half_rn(sum);
        if (tx == 0) { g_asrc2[row] = ss; g_adst2[row] = sd; }
    }
}

// ---------------- layer2 gather: 4 lanes per node, 4-edge index batching -----
__global__ __launch_bounds__(256) void gather2_kernel(const float* __restrict__ bias,
                                                      float* __restrict__ out) {
    int gid = blockIdx.x * blockDim.x + threadIdx.x;
    int n = gid >> 2;
    int q = gid & 3;
    if (n >= N_NODES) return;
    float adv = g_adst2[n];
    int j = g_off[n], jend = g_off[n + 1];
    float4 acc = make_float4(0.f, 0.f, 0.f, 0.f);
    float dsum = 0.0f;
    for (; j + 3 < jend; j += 4) {
        int s0 = g_csr_src[j];
        int s1 = g_csr_src[j + 1];
        int s2 = g_csr_src[j + 2];
        int s3 = g_csr_src[j + 3];
        float a0 = g_asrc2[s0];
        float a1 = g_asrc2[s1];
        float a2 = g_asrc2[s2];
        float a3 = g_asrc2[s3];
        uint2 r0 = *(const uint2*)&g_h2h[s0 * 16 + q * 4];
        uint2 r1 = *(const uint2*)&g_h2h[s1 * 16 + q * 4];
        uint2 r2 = *(const uint2*)&g_h2h[s2 * 16 + q * 4];
        uint2 r3 = *(const uint2*)&g_h2h[s3 * 16 + q * 4];
        float e0 = __expf(lrelu(a0 + adv));
        float e1 = __expf(lrelu(a1 + adv));
        float e2 = __expf(lrelu(a2 + adv));
        float e3 = __expf(lrelu(a3 + adv));
        facc4(acc, r0, e0);
        facc4(acc, r1, e1);
        facc4(acc, r2, e2);
        facc4(acc, r3, e3);
        dsum += (e0 + e1) + (e2 + e3);
    }
    for (; j < jend; j++) {
        int sa = g_csr_src[j];
        float ea = __expf(lrelu(g_asrc2[sa] + adv));
        uint2 rw = *(const uint2*)&g_h2h[sa * 16 + q * 4];
        facc4(acc, rw, ea);
        dsum += ea;
    }
    float inv = 1.0f / dsum;
    float4 b = *(const float4*)&bias[q * 4];
    float4 v;
    v.x = acc.x * inv + b.x;
    v.y = acc.y * inv + b.y;
    v.z = acc.z * inv + b.z;
    v.w = acc.w * inv + b.w;
    *(float4*)&out[n * 16 + q * 4] = v;
}

// ---------------- launch ------------------------------------------------------
extern "C" void kernel_launch(void* const* d_in, const int* in_sizes, int n_in,
                              void* d_out, int out_size) {
    const float* x      = (const float*)d_in[0];
    const int*   ei     = (const int*)d_in[1];
    const float* W1     = (const float*)d_in[2];
    const float* att_s1 = (const float*)d_in[3];
    const float* att_d1 = (const float*)d_in[4];
    const float* b1     = (const float*)d_in[5];
    const float* W2     = (const float*)d_in[6];
    const float* att_s2 = (const float*)d_in[7];
    const float* att_d2 = (const float*)d_in[8];
    const float* b2     = (const float*)d_in[9];
    float* out = (float*)d_out;
    const int* src = ei;
    const int* dst = ei + N_EDGES;

    // g_deg is zero on entry (zero-init at load; scatter re-zeroes every call)
    count_kernel<<<(E_TOT + 255) / 256, 256>>>(dst);          // 0
    scanA_kernel<<<NBLK_SCAN, 256>>>();                       // 1
    scanC_kernel<<<NBLK_SCAN, 256>>>();                       // 2
    gemm1_kernel<<<(N_NODES + 127) / 128, 256>>>(x, W1, att_s1, att_d1);  // 3 <- profiled
    scatter_kernel<<<(E_TOT + 255) / 256, 256>>>(src, dst);   // 4
    gather1_kernel<<<(N_NODES * 32 + 255) / 256, 256>>>(b1);  // 5
    gemm2_kernel<<<(N_NODES + 15) / 16, 256>>>(W2, att_s2, att_d2);       // 6
    gather2_kernel<<<(N_NODES * 4 + 255) / 256, 256>>>(b2, out);          // 7
}

// round 13
// speedup vs baseline: 1.8403x; 1.2905x over previous
#include <cuda_runtime.h>
#include <cuda_fp16.h>

#define N_NODES 50000
#define N_EDGES 1600000
#define E_TOT   (N_EDGES + N_NODES)
#define IN_C    256
#define HID_C   128
#define OUT_C   16
#define HEADS   8
#define NBLK_SCAN 49   // ceil(50000/1024)

// ---------------- scratch (device globals; zero-initialized at load) ---------
__device__ __align__(256) __half g_h1h[N_NODES * HID_C];     // fp16 messages L1
__device__ __align__(256) float  g_asrc1[N_NODES * HEADS];
__device__ __align__(256) float  g_adst1[N_NODES * HEADS];
__device__ __align__(256) __half g_hreluh[N_NODES * HID_C];  // fp16 layer1 out
__device__ __align__(256) __half g_h2h[N_NODES * OUT_C];     // fp16 messages L2
__device__ __align__(256) float  g_asrc2[N_NODES];
__device__ __align__(256) float  g_adst2[N_NODES];
__device__ __align__(256) int    g_deg[N_NODES];   // zeroed at end of scatter
__device__ __align__(256) int    g_off[N_NODES + 1];
__device__ __align__(256) int    g_cursor[N_NODES];
__device__ __align__(256) int    g_part[64];
__device__ __align__(256) int    g_csr_src[E_TOT];

__device__ __forceinline__ float lrelu(float a) {
    return a > 0.0f ? a : 0.2f * a;
}

__device__ __forceinline__ void mma_f16(float* d, const unsigned* a, const unsigned* b) {
    asm volatile(
        "mma.sync.aligned.m16n8k16.row.col.f32.f16.f16.f32 "
        "{%0,%1,%2,%3}, {%4,%5,%6,%7}, {%8,%9}, {%0,%1,%2,%3};\n"
        : "+f"(d[0]), "+f"(d[1]), "+f"(d[2]), "+f"(d[3])
        : "r"(a[0]), "r"(a[1]), "r"(a[2]), "r"(a[3]), "r"(b[0]), "r"(b[1]));
}

__device__ __forceinline__ void ldsm_x4(unsigned& r0, unsigned& r1, unsigned& r2,
                                        unsigned& r3, unsigned addr) {
    asm volatile("ldmatrix.sync.aligned.m8n8.x4.shared.b16 {%0,%1,%2,%3}, [%4];"
                 : "=r"(r0), "=r"(r1), "=r"(r2), "=r"(r3) : "r"(addr));
}

__device__ __forceinline__ void ldsm_x4_t(unsigned& r0, unsigned& r1, unsigned& r2,
                                          unsigned& r3, unsigned addr) {
    asm volatile("ldmatrix.sync.aligned.m8n8.x4.trans.shared.b16 {%0,%1,%2,%3}, [%4];"
                 : "=r"(r0), "=r"(r1), "=r"(r2), "=r"(r3) : "r"(addr));
}

__device__ __forceinline__ uint2 f4_to_h4(float4 v) {
    __half2 lo = __floats2half2_rn(v.x, v.y);
    __half2 hi = __floats2half2_rn(v.z, v.w);
    uint2 r;
    r.x = *(unsigned*)&lo;
    r.y = *(unsigned*)&hi;
    return r;
}

// accumulate 4 fp16 channels (uint2) weighted by e into float4
__device__ __forceinline__ void facc4(float4& acc, uint2 rw, float e) {
    float2 f01 = __half22float2(*(__half2*)&rw.x);
    float2 f23 = __half22float2(*(__half2*)&rw.y);
    acc.x += f01.x * e;
    acc.y += f01.y * e;
    acc.z += f23.x * e;
    acc.w += f23.y * e;
}

// ---------------- CSR build ---------------------------------------------------
__global__ void count_kernel(const int* __restrict__ dst) {
    int e = blockIdx.x * blockDim.x + threadIdx.x;
    if (e >= E_TOT) return;
    int d = (e < N_EDGES) ? dst[e] : e - N_EDGES;
    atomicAdd(&g_deg[d], 1);
}

__global__ void scanA_kernel() {
    __shared__ int sh[8];
    int b = blockIdx.x, t = threadIdx.x;
    int base = b * 1024 + t * 4;
    int s = 0;
#pragma unroll
    for (int k = 0; k < 4; k++) { int i = base + k; if (i < N_NODES) s += g_deg[i]; }
#pragma unroll
    for (int o = 16; o; o >>= 1) s += __shfl_xor_sync(0xffffffffu, s, o);
    if ((t & 31) == 0) sh[t >> 5] = s;
    __syncthreads();
    if (t < 8) {
        int v = sh[t];
#pragma unroll
        for (int o = 4; o; o >>= 1) v += __shfl_xor_sync(0xffffffffu, v, o);
        if (t == 0) g_part[b] = v;
    }
}

__global__ void scanC_kernel() {
    __shared__ int ws[8];
    __shared__ int s_pre;
    int b = blockIdx.x, t = threadIdx.x;
    int lane = t & 31, w = t >> 5;
    if (w == 0) {
        int v = 0;
        if (lane < b && lane < NBLK_SCAN) v = g_part[lane];
        if (lane + 32 < b && lane + 32 < NBLK_SCAN) v += g_part[lane + 32];
#pragma unroll
        for (int o = 16; o; o >>= 1) v += __shfl_xor_sync(0xffffffffu, v, o);
        if (lane == 0) s_pre = v;
    }
    int base = b * 1024 + t * 4;
    int d0 = 0, d1 = 0, d2 = 0, d3 = 0;
    if (base + 0 < N_NODES) d0 = g_deg[base + 0];
    if (base + 1 < N_NODES) d1 = g_deg[base + 1];
    if (base + 2 < N_NODES) d2 = g_deg[base + 2];
    if (base + 3 < N_NODES) d3 = g_deg[base + 3];
    int tsum = d0 + d1 + d2 + d3;
    int v = tsum;
#pragma unroll
    for (int o = 1; o < 32; o <<= 1) {
        int u = __shfl_up_sync(0xffffffffu, v, o);
        if (lane >= o) v += u;
    }
    if (lane == 31) ws[w] = v;
    __syncthreads();
    int woff = 0;
    for (int i = 0; i < w; i++) woff += ws[i];
    int excl = v - tsum + woff + s_pre;
    int o0 = excl, o1 = o0 + d0, o2 = o1 + d1, o3 = o2 + d2;
    if (base + 0 < N_NODES) { g_off[base + 0] = o0; g_cursor[base + 0] = o0; }
    if (base + 1 < N_NODES) { g_off[base + 1] = o1; g_cursor[base + 1] = o1; }
    if (base + 2 < N_NODES) { g_off[base + 2] = o2; g_cursor[base + 2] = o2; }
    if (base + 3 < N_NODES) { g_off[base + 3] = o3; g_cursor[base + 3] = o3; }
    if (b == 0 && t == 0) g_off[N_NODES] = E_TOT;
}

__global__ void scatter_kernel(const int* __restrict__ src, const int* __restrict__ dst) {
    int e = blockIdx.x * blockDim.x + threadIdx.x;
    if (e < E_TOT) {
        int s, d;
        if (e < N_EDGES) { s = src[e]; d = dst[e]; }
        else             { s = d = e - N_EDGES; }
        int pos = atomicAdd(&g_cursor[d], 1);
        g_csr_src[pos] = s;
    }
    if (e < N_NODES) g_deg[e] = 0;
}

// ---------------- GEMM1 (fp16 HMMA + ldmatrix) + fused att + fp16 h1 ---------
// BM=128 BN=128 BK=32, 256 threads (8 warps: 4x2), warp tile 32x64.
// A smem: [128 m][32 k] fp16 stride 40; B smem: [32 k][128 n] fp16 stride 136.
#define ASTR 40
#define BSTR 136
__global__ __launch_bounds__(256) void gemm1_kernel(const float* __restrict__ A,
                                                    const float* __restrict__ B,
                                                    const float* __restrict__ att_s,
                                                    const float* __restrict__ att_d) {
    __shared__ __half As[2][128 * ASTR];
    __shared__ __half Bs[2][32 * BSTR];
    const int M = N_NODES;
    int rowBase = blockIdx.x * 128;
    int tid = threadIdx.x;
    int lane = tid & 31;
    int warpId = tid >> 5;
    int wmRow = (warpId >> 1) * 32;
    int wnCol = (warpId & 1) * 64;

    // per-thread tile-load coords: 4 float4 each for A and B per chunk
    int arow[4], akc[4], brow[4], bnc[4];
#pragma unroll
    for (int p = 0; p < 4; p++) {
        int fidx = tid + p * 256;          // 0..1023
        arow[p] = fidx >> 3;               // 128 rows, 8 float4/row (32 k)
        akc[p] = (fidx & 7) * 4;
        brow[p] = fidx >> 5;               // 32 k-rows, 32 float4/row (128 n)
        bnc[p] = (fidx & 31) * 4;
    }

    float acc[2][8][4];
#pragma unroll
    for (int i = 0; i < 2; i++)
#pragma unroll
        for (int j = 0; j < 8; j++)
#pragma unroll
            for (int q = 0; q < 4; q++) acc[i][j][q] = 0.0f;

    // ldmatrix base addresses (lane-dependent)
    unsigned aShared0 = (unsigned)__cvta_generic_to_shared(&As[0][0]);
    unsigned bShared0 = (unsigned)__cvta_generic_to_shared(&Bs[0][0]);
    unsigned aBufBytes = 128 * ASTR * 2;
    unsigned bBufBytes = 32 * BSTR * 2;
    int aLaneRow = lane & 15;               // m-row offset within 16
    int aLaneK = ((lane >> 4) & 1) * 8;     // k offset 0/8
    int bLaneK = lane & 15;                 // k-row offset within 16
    int bLaneN = ((lane >> 4) & 1) * 8;     // n offset 0/8

    // ---- prologue: chunk 0 ----
#pragma unroll
    for (int p = 0; p < 4; p++) {
        int gr = rowBase + arow[p];
        float4 av = make_float4(0.f, 0.f, 0.f, 0.f);
        if (gr < M) av = *(const float4*)&A[(long)gr * IN_C + akc[p]];
        *(uint2*)&As[0][arow[p] * ASTR + akc[p]] = f4_to_h4(av);
        float4 bv = *(const float4*)&B[brow[p] * 128 + bnc[p]];
        *(uint2*)&Bs[0][brow[p] * BSTR + bnc[p]] = f4_to_h4(bv);
    }
    __syncthreads();

    uint2 sa[4], sb[4];
    for (int c = 0; c < 8; c++) {
        int buf = c & 1;
        if (c < 7) {
            int kbase = (c + 1) * 32;
#pragma unroll
            for (int p = 0; p < 4; p++) {
                int gr = rowBase + arow[p];
                float4 av = make_float4(0.f, 0.f, 0.f, 0.f);
                if (gr < M) av = *(const float4*)&A[(long)gr * IN_C + kbase + akc[p]];
                sa[p] = f4_to_h4(av);
                float4 bv = *(const float4*)&B[(kbase + brow[p]) * 128 + bnc[p]];
                sb[p] = f4_to_h4(bv);
            }
        }
        unsigned aBase = aShared0 + buf * aBufBytes;
        unsigned bBase = bShared0 + buf * bBufBytes;
#pragma unroll
        for (int ks = 0; ks < 2; ks++) {
            int k0 = ks * 16;
            unsigned ua[2][4];
#pragma unroll
            for (int mi = 0; mi < 2; mi++) {
                unsigned addr = aBase +
                    ((wmRow + mi * 16 + aLaneRow) * ASTR + k0 + aLaneK) * 2;
                ldsm_x4(ua[mi][0], ua[mi][1], ua[mi][2], ua[mi][3], addr);
            }
#pragma unroll
            for (int ng = 0; ng < 4; ng++) {
                int n0 = wnCol + ng * 16;
                unsigned addr = bBase +
                    ((k0 + bLaneK) * BSTR + n0 + bLaneN) * 2;
                unsigned r0, r1, r2, r3;
                ldsm_x4_t(r0, r1, r2, r3, addr);
                unsigned b0[2] = { r0, r1 };
                unsigned b1[2] = { r2, r3 };
                mma_f16(acc[0][ng * 2 + 0], ua[0], b0);
                mma_f16(acc[1][ng * 2 + 0], ua[1], b0);
                mma_f16(acc[0][ng * 2 + 1], ua[0], b1);
                mma_f16(acc[1][ng * 2 + 1], ua[1], b1);
            }
        }
        if (c < 7) {
            int nb_ = buf ^ 1;
#pragma unroll
            for (int p = 0; p < 4; p++) {
                *(uint2*)&As[nb_][arow[p] * ASTR + akc[p]] = sa[p];
                *(uint2*)&Bs[nb_][brow[p] * BSTR + bnc[p]] = sb[p];
            }
        }
        __syncthreads();
    }

    // ---- epilogue 1: fp16 h1 stores (m16n8 frag: c0/c1 row g, c2/c3 row g+8) ----
#pragma unroll
    for (int mi = 0; mi < 2; mi++) {
#pragma unroll
        for (int nj = 0; nj < 8; nj++) {
            int r0 = rowBase + wmRow + mi * 16 + (lane >> 2);
            int col = wnCol + nj * 8 + (lane & 3) * 2;
            if (r0 < M)
                *(__half2*)&g_h1h[r0 * 128 + col] = __floats2half2_rn(acc[mi][nj][0], acc[mi][nj][1]);
            if (r0 + 8 < M)
                *(__half2*)&g_h1h[(r0 + 8) * 128 + col] = __floats2half2_rn(acc[mi][nj][2], acc[mi][nj][3]);
        }
    }

    // ---- epilogue 2: fused attention scores (per-head dots) ----
    float s_part[2][2][4], d_part[2][2][4];
#pragma unroll
    for (int mi = 0; mi < 2; mi++)
#pragma unroll
        for (int r = 0; r < 2; r++)
#pragma unroll
            for (int hh = 0; hh < 4; hh++) { s_part[mi][r][hh] = 0.f; d_part[mi][r][hh] = 0.f; }

#pragma unroll
    for (int mi = 0; mi < 2; mi++) {
#pragma unroll
        for (int nj = 0; nj < 8; nj++) {
            int hh = nj >> 1;
            int ch0 = wnCol + nj * 8 + (lane & 3) * 2;
            float as0 = att_s[ch0], as1 = att_s[ch0 + 1];
            float ad0 = att_d[ch0], ad1 = att_d[ch0 + 1];
            s_part[mi][0][hh] += acc[mi][nj][0] * as0 + acc[mi][nj][1] * as1;
            d_part[mi][0][hh] += acc[mi][nj][0] * ad0 + acc[mi][nj][1] * ad1;
            s_part[mi][1][hh] += acc[mi][nj][2] * as0 + acc[mi][nj][3] * as1;
            d_part[mi][1][hh] += acc[mi][nj][2] * ad0 + acc[mi][nj][3] * ad1;
        }
    }
#pragma unroll
    for (int mi = 0; mi < 2; mi++)
#pragma unroll
        for (int r = 0; r < 2; r++)
#pragma unroll
            for (int hh = 0; hh < 4; hh++) {
                float vs = s_part[mi][r][hh], vd = d_part[mi][r][hh];
                vs += __shfl_xor_sync(0xffffffffu, vs, 1);
                vs += __shfl_xor_sync(0xffffffffu, vs, 2);
                vd += __shfl_xor_sync(0xffffffffu, vd, 1);
                vd += __shfl_xor_sync(0xffffffffu, vd, 2);
                s_part[mi][r][hh] = vs;
                d_part[mi][r][hh] = vd;
            }
    if ((lane & 3) == 0) {
        int hbase = wnCol >> 4;
#pragma unroll
        for (int mi = 0; mi < 2; mi++) {
            int r0 = rowBase + wmRow + mi * 16 + (lane >> 2);
#pragma unroll
            for (int r = 0; r < 2; r++) {
                int row = r0 + r * 8;
                if (row < M) {
#pragma unroll
                    for (int hh = 0; hh < 4; hh++) {
                        g_asrc1[row * 8 + hbase + hh] = s_part[mi][r][hh];
                        g_adst1[row * 8 + hbase + hh] = d_part[mi][r][hh];
                    }
                }
            }
        }
    }
}

// ---------------- layer1 gather: warp per node, 4-edge index batching --------
__global__ __launch_bounds__(256) void gather1_kernel(const float* __restrict__ bias) {
    int n = (blockIdx.x * blockDim.x + threadIdx.x) >> 5;
    int lane = threadIdx.x & 31;
    if (n >= N_NODES) return;
    int h = lane >> 2;
    float adv = g_adst1[n * 8 + h];
    int j = g_off[n], jend = g_off[n + 1];
    float4 acc = make_float4(0.f, 0.f, 0.f, 0.f);
    float dsum = 0.0f;
    for (; j + 3 < jend; j += 4) {
        int s0 = g_csr_src[j];
        int s1 = g_csr_src[j + 1];
        int s2 = g_csr_src[j + 2];
        int s3 = g_csr_src[j + 3];
        float a0 = g_asrc1[s0 * 8 + h];
        float a1 = g_asrc1[s1 * 8 + h];
        float a2 = g_asrc1[s2 * 8 + h];
        float a3 = g_asrc1[s3 * 8 + h];
        uint2 r0 = *(const uint2*)&g_h1h[s0 * 128 + lane * 4];
        uint2 r1 = *(const uint2*)&g_h1h[s1 * 128 + lane * 4];
        uint2 r2 = *(const uint2*)&g_h1h[s2 * 128 + lane * 4];
        uint2 r3 = *(const uint2*)&g_h1h[s3 * 128 + lane * 4];
        float e0 = __expf(lrelu(a0 + adv));
        float e1 = __expf(lrelu(a1 + adv));
        float e2 = __expf(lrelu(a2 + adv));
        float e3 = __expf(lrelu(a3 + adv));
        facc4(acc, r0, e0);
        facc4(acc, r1, e1);
        facc4(acc, r2, e2);
        facc4(acc, r3, e3);
        dsum += (e0 + e1) + (e2 + e3);
    }
    for (; j < jend; j++) {
        int sa = g_csr_src[j];
        float ea = __expf(lrelu(g_asrc1[sa * 8 + h] + adv));
        uint2 rw = *(const uint2*)&g_h1h[sa * 128 + lane * 4];
        facc4(acc, rw, ea);
        dsum += ea;
    }
    float inv = 1.0f / dsum;
    float4 b = *(const float4*)&bias[lane * 4];
    __half2 o01 = __floats2half2_rn(fmaxf(acc.x * inv + b.x, 0.0f),
                                    fmaxf(acc.y * inv + b.y, 0.0f));
    __half2 o23 = __floats2half2_rn(fmaxf(acc.z * inv + b.z, 0.0f),
                                    fmaxf(acc.w * inv + b.w, 0.0f));
    uint2 ov;
    ov.x = *(unsigned*)&o01;
    ov.y = *(unsigned*)&o23;
    *(uint2*)&g_hreluh[n * 128 + lane * 4] = ov;
}

// ---------------- GEMM2 (+ fused a_src2/a_dst2): h2 = hrelu @ W2 -------------
__global__ __launch_bounds__(256) void gemm2_kernel(const float* __restrict__ W2,
                                                    const float* __restrict__ att_s,
                                                    const float* __restrict__ att_d) {
    __shared__ float Ws[128 * 16];
    __shared__ float Hs[16][128];
    int tid = threadIdx.x;
    int base = blockIdx.x * 16;
    for (int i = tid; i < 128 * 16; i += 256) Ws[i] = W2[i];
    for (int i = tid; i < 16 * 128; i += 256) {
        int r = i >> 7, c = i & 127;
        int gr = base + r;
        Hs[r][c] = (gr < N_NODES) ? __half2float(g_hreluh[gr * 128 + c]) : 0.0f;
    }
    __syncthreads();
    int ty = tid >> 4, tx = tid & 15;
    float sum = 0.0f;
#pragma unroll 8
    for (int k = 0; k < 128; k++) sum += Hs[ty][k] * Ws[k * 16 + tx];
    float ss = sum * att_s[tx];
    float sd = sum * att_d[tx];
#pragma unroll
    for (int off = 8; off; off >>= 1) {
        ss += __shfl_xor_sync(0xffffffffu, ss, off);
        sd += __shfl_xor_sync(0xffffffffu, sd, off);
    }
    int row = base + ty;
    if (row < N_NODES) {
        g_h2h[row * 16 + tx] = __float2half_rn(sum);
        if (tx == 0) { g_asrc2[row] = ss; g_adst2[row] = sd; }
    }
}

// ---------------- layer2 gather: 4 lanes per node, 4-edge index batching -----
__global__ __launch_bounds__(256) void gather2_kernel(const float* __restrict__ bias,
                                                      float* __restrict__ out) {
    int gid = blockIdx.x * blockDim.x + threadIdx.x;
    int n = gid >> 2;
    int q = gid & 3;
    if (n >= N_NODES) return;
    float adv = g_adst2[n];
    int j = g_off[n], jend = g_off[n + 1];
    float4 acc = make_float4(0.f, 0.f, 0.f, 0.f);
    float dsum = 0.0f;
    for (; j + 3 < jend; j += 4) {
        int s0 = g_csr_src[j];
        int s1 = g_csr_src[j + 1];
        int s2 = g_csr_src[j + 2];
        int s3 = g_csr_src[j + 3];
        float a0 = g_asrc2[s0];
        float a1 = g_asrc2[s1];
        float a2 = g_asrc2[s2];
        float a3 = g_asrc2[s3];
        uint2 r0 = *(const uint2*)&g_h2h[s0 * 16 + q * 4];
        uint2 r1 = *(const uint2*)&g_h2h[s1 * 16 + q * 4];
        uint2 r2 = *(const uint2*)&g_h2h[s2 * 16 + q * 4];
        uint2 r3 = *(const uint2*)&g_h2h[s3 * 16 + q * 4];
        float e0 = __expf(lrelu(a0 + adv));
        float e1 = __expf(lrelu(a1 + adv));
        float e2 = __expf(lrelu(a2 + adv));
        float e3 = __expf(lrelu(a3 + adv));
        facc4(acc, r0, e0);
        facc4(acc, r1, e1);
        facc4(acc, r2, e2);
        facc4(acc, r3, e3);
        dsum += (e0 + e1) + (e2 + e3);
    }
    for (; j < jend; j++) {
        int sa = g_csr_src[j];
        float ea = __expf(lrelu(g_asrc2[sa] + adv));
        uint2 rw = *(const uint2*)&g_h2h[sa * 16 + q * 4];
        facc4(acc, rw, ea);
        dsum += ea;
    }
    float inv = 1.0f / dsum;
    float4 b = *(const float4*)&bias[q * 4];
    float4 v;
    v.x = acc.x * inv + b.x;
    v.y = acc.y * inv + b.y;
    v.z = acc.z * inv + b.z;
    v.w = acc.w * inv + b.w;
    *(float4*)&out[n * 16 + q * 4] = v;
}

// ---------------- launch ------------------------------------------------------
extern "C" void kernel_launch(void* const* d_in, const int* in_sizes, int n_in,
                              void* d_out, int out_size) {
    const float* x      = (const float*)d_in[0];
    const int*   ei     = (const int*)d_in[1];
    const float* W1     = (const float*)d_in[2];
    const float* att_s1 = (const float*)d_in[3];
    const float* att_d1 = (const float*)d_in[4];
    const float* b1     = (const float*)d_in[5];
    const float* W2     = (const float*)d_in[6];
    const float* att_s2 = (const float*)d_in[7];
    const float* att_d2 = (const float*)d_in[8];
    const float* b2     = (const float*)d_in[9];
    float* out = (float*)d_out;
    const int* src = ei;
    const int* dst = ei + N_EDGES;

    count_kernel<<<(E_TOT + 255) / 256, 256>>>(dst);          // 0
    scanA_kernel<<<NBLK_SCAN, 256>>>();                       // 1
    scanC_kernel<<<NBLK_SCAN, 256>>>();                       // 2
    gemm1_kernel<<<(N_NODES + 127) / 128, 256>>>(x, W1, att_s1, att_d1);  // 3 <- profiled
    scatter_kernel<<<(E_TOT + 255) / 256, 256>>>(src, dst);   // 4
    gather1_kernel<<<(N_NODES * 32 + 255) / 256, 256>>>(b1);  // 5
    gemm2_kernel<<<(N_NODES + 15) / 16, 256>>>(W2, att_s2, att_d2);       // 6
    gather2_kernel<<<(N_NODES * 4 + 255) / 256, 256>>>(b2, out);          // 7
}

// round 14
// speedup vs baseline: 1.9442x; 1.0565x over previous
#include <cuda_runtime.h>
#include <cuda_fp16.h>

#define N_NODES 50000
#define N_EDGES 1600000
#define E_TOT   (N_EDGES + N_NODES)
#define IN_C    256
#define HID_C   128
#define OUT_C   16
#define HEADS   8
#define NBLK_SCAN 49   // ceil(50000/1024)

// ---------------- scratch (device globals; zero-initialized at load) ---------
__device__ __align__(256) __half g_h1h[N_NODES * HID_C];     // fp16 messages L1
__device__ __align__(256) float  g_asrc1[N_NODES * HEADS];
__device__ __align__(256) float  g_adst1[N_NODES * HEADS];
__device__ __align__(256) __half g_hreluh[N_NODES * HID_C];  // fp16 layer1 out
__device__ __align__(256) __half g_h2h[N_NODES * OUT_C];     // fp16 messages L2
__device__ __align__(256) float  g_asrc2[N_NODES];
__device__ __align__(256) float  g_adst2[N_NODES];
__device__ __align__(256) int    g_deg[N_NODES];   // zeroed at end of scatter
__device__ __align__(256) int    g_off[N_NODES + 1];
__device__ __align__(256) int    g_cursor[N_NODES];
__device__ __align__(256) int    g_part[64];
__device__ __align__(256) int    g_csr_src[E_TOT];

__device__ __forceinline__ float lrelu(float a) {
    return a > 0.0f ? a : 0.2f * a;
}

__device__ __forceinline__ void mma_f16(float* d, const unsigned* a, const unsigned* b) {
    asm volatile(
        "mma.sync.aligned.m16n8k16.row.col.f32.f16.f16.f32 "
        "{%0,%1,%2,%3}, {%4,%5,%6,%7}, {%8,%9}, {%0,%1,%2,%3};\n"
        : "+f"(d[0]), "+f"(d[1]), "+f"(d[2]), "+f"(d[3])
        : "r"(a[0]), "r"(a[1]), "r"(a[2]), "r"(a[3]), "r"(b[0]), "r"(b[1]));
}

__device__ __forceinline__ void ldsm_x4(unsigned& r0, unsigned& r1, unsigned& r2,
                                        unsigned& r3, unsigned addr) {
    asm volatile("ldmatrix.sync.aligned.m8n8.x4.shared.b16 {%0,%1,%2,%3}, [%4];"
                 : "=r"(r0), "=r"(r1), "=r"(r2), "=r"(r3) : "r"(addr));
}

__device__ __forceinline__ void ldsm_x4_t(unsigned& r0, unsigned& r1, unsigned& r2,
                                          unsigned& r3, unsigned addr) {
    asm volatile("ldmatrix.sync.aligned.m8n8.x4.trans.shared.b16 {%0,%1,%2,%3}, [%4];"
                 : "=r"(r0), "=r"(r1), "=r"(r2), "=r"(r3) : "r"(addr));
}

__device__ __forceinline__ uint2 f4_to_h4(float4 v) {
    __half2 lo = __floats2half2_rn(v.x, v.y);
    __half2 hi = __floats2half2_rn(v.z, v.w);
    uint2 r;
    r.x = *(unsigned*)&lo;
    r.y = *(unsigned*)&hi;
    return r;
}

// accumulate 4 fp16 channels (uint2) weighted by e into float4
__device__ __forceinline__ void facc4(float4& acc, uint2 rw, float e) {
    float2 f01 = __half22float2(*(__half2*)&rw.x);
    float2 f23 = __half22float2(*(__half2*)&rw.y);
    acc.x += f01.x * e;
    acc.y += f01.y * e;
    acc.z += f23.x * e;
    acc.w += f23.y * e;
}

// ---------------- CSR build ---------------------------------------------------
__global__ void count_kernel(const int* __restrict__ dst) {
    int e = blockIdx.x * blockDim.x + threadIdx.x;
    if (e >= E_TOT) return;
    int d = (e < N_EDGES) ? dst[e] : e - N_EDGES;
    atomicAdd(&g_deg[d], 1);
}

__global__ void scanA_kernel() {
    __shared__ int sh[8];
    int b = blockIdx.x, t = threadIdx.x;
    int base = b * 1024 + t * 4;
    int s = 0;
#pragma unroll
    for (int k = 0; k < 4; k++) { int i = base + k; if (i < N_NODES) s += g_deg[i]; }
#pragma unroll
    for (int o = 16; o; o >>= 1) s += __shfl_xor_sync(0xffffffffu, s, o);
    if ((t & 31) == 0) sh[t >> 5] = s;
    __syncthreads();
    if (t < 8) {
        int v = sh[t];
#pragma unroll
        for (int o = 4; o; o >>= 1) v += __shfl_xor_sync(0xffffffffu, v, o);
        if (t == 0) g_part[b] = v;
    }
}

__global__ void scanC_kernel() {
    __shared__ int ws[8];
    __shared__ int s_pre;
    int b = blockIdx.x, t = threadIdx.x;
    int lane = t & 31, w = t >> 5;
    if (w == 0) {
        int v = 0;
        if (lane < b && lane < NBLK_SCAN) v = g_part[lane];
        if (lane + 32 < b && lane + 32 < NBLK_SCAN) v += g_part[lane + 32];
#pragma unroll
        for (int o = 16; o; o >>= 1) v += __shfl_xor_sync(0xffffffffu, v, o);
        if (lane == 0) s_pre = v;
    }
    int base = b * 1024 + t * 4;
    int d0 = 0, d1 = 0, d2 = 0, d3 = 0;
    if (base + 0 < N_NODES) d0 = g_deg[base + 0];
    if (base + 1 < N_NODES) d1 = g_deg[base + 1];
    if (base + 2 < N_NODES) d2 = g_deg[base + 2];
    if (base + 3 < N_NODES) d3 = g_deg[base + 3];
    int tsum = d0 + d1 + d2 + d3;
    int v = tsum;
#pragma unroll
    for (int o = 1; o < 32; o <<= 1) {
        int u = __shfl_up_sync(0xffffffffu, v, o);
        if (lane >= o) v += u;
    }
    if (lane == 31) ws[w] = v;
    __syncthreads();
    int woff = 0;
    for (int i = 0; i < w; i++) woff += ws[i];
    int excl = v - tsum + woff + s_pre;
    int o0 = excl, o1 = o0 + d0, o2 = o1 + d1, o3 = o2 + d2;
    if (base + 0 < N_NODES) { g_off[base + 0] = o0; g_cursor[base + 0] = o0; }
    if (base + 1 < N_NODES) { g_off[base + 1] = o1; g_cursor[base + 1] = o1; }
    if (base + 2 < N_NODES) { g_off[base + 2] = o2; g_cursor[base + 2] = o2; }
    if (base + 3 < N_NODES) { g_off[base + 3] = o3; g_cursor[base + 3] = o3; }
    if (b == 0 && t == 0) g_off[N_NODES] = E_TOT;
}

__global__ void scatter_kernel(const int* __restrict__ src, const int* __restrict__ dst) {
    int e = blockIdx.x * blockDim.x + threadIdx.x;
    if (e < E_TOT) {
        int s, d;
        if (e < N_EDGES) { s = src[e]; d = dst[e]; }
        else             { s = d = e - N_EDGES; }
        int pos = atomicAdd(&g_cursor[d], 1);
        g_csr_src[pos] = s;
    }
    if (e < N_NODES) g_deg[e] = 0;
}

// ---------------- GEMM1 (fp16 HMMA + ldmatrix) + fused att + fp16 h1 ---------
#define ASTR 40
#define BSTR 136
__global__ __launch_bounds__(256) void gemm1_kernel(const float* __restrict__ A,
                                                    const float* __restrict__ B,
                                                    const float* __restrict__ att_s,
                                                    const float* __restrict__ att_d) {
    __shared__ __half As[2][128 * ASTR];
    __shared__ __half Bs[2][32 * BSTR];
    const int M = N_NODES;
    int rowBase = blockIdx.x * 128;
    int tid = threadIdx.x;
    int lane = tid & 31;
    int warpId = tid >> 5;
    int wmRow = (warpId >> 1) * 32;
    int wnCol = (warpId & 1) * 64;

    int arow[4], akc[4], brow[4], bnc[4];
#pragma unroll
    for (int p = 0; p < 4; p++) {
        int fidx = tid + p * 256;
        arow[p] = fidx >> 3;
        akc[p] = (fidx & 7) * 4;
        brow[p] = fidx >> 5;
        bnc[p] = (fidx & 31) * 4;
    }

    float acc[2][8][4];
#pragma unroll
    for (int i = 0; i < 2; i++)
#pragma unroll
        for (int j = 0; j < 8; j++)
#pragma unroll
            for (int q = 0; q < 4; q++) acc[i][j][q] = 0.0f;

    unsigned aShared0 = (unsigned)__cvta_generic_to_shared(&As[0][0]);
    unsigned bShared0 = (unsigned)__cvta_generic_to_shared(&Bs[0][0]);
    unsigned aBufBytes = 128 * ASTR * 2;
    unsigned bBufBytes = 32 * BSTR * 2;
    int aLaneRow = lane & 15;
    int aLaneK = ((lane >> 4) & 1) * 8;
    int bLaneK = lane & 15;
    int bLaneN = ((lane >> 4) & 1) * 8;

#pragma unroll
    for (int p = 0; p < 4; p++) {
        int gr = rowBase + arow[p];
        float4 av = make_float4(0.f, 0.f, 0.f, 0.f);
        if (gr < M) av = *(const float4*)&A[(long)gr * IN_C + akc[p]];
        *(uint2*)&As[0][arow[p] * ASTR + akc[p]] = f4_to_h4(av);
        float4 bv = *(const float4*)&B[brow[p] * 128 + bnc[p]];
        *(uint2*)&Bs[0][brow[p] * BSTR + bnc[p]] = f4_to_h4(bv);
    }
    __syncthreads();

    uint2 sa[4], sb[4];
    for (int c = 0; c < 8; c++) {
        int buf = c & 1;
        if (c < 7) {
            int kbase = (c + 1) * 32;
#pragma unroll
            for (int p = 0; p < 4; p++) {
                int gr = rowBase + arow[p];
                float4 av = make_float4(0.f, 0.f, 0.f, 0.f);
                if (gr < M) av = *(const float4*)&A[(long)gr * IN_C + kbase + akc[p]];
                sa[p] = f4_to_h4(av);
                float4 bv = *(const float4*)&B[(kbase + brow[p]) * 128 + bnc[p]];
                sb[p] = f4_to_h4(bv);
            }
        }
        unsigned aBase = aShared0 + buf * aBufBytes;
        unsigned bBase = bShared0 + buf * bBufBytes;
#pragma unroll
        for (int ks = 0; ks < 2; ks++) {
            int k0 = ks * 16;
            unsigned ua[2][4];
#pragma unroll
            for (int mi = 0; mi < 2; mi++) {
                unsigned addr = aBase +
                    ((wmRow + mi * 16 + aLaneRow) * ASTR + k0 + aLaneK) * 2;
                ldsm_x4(ua[mi][0], ua[mi][1], ua[mi][2], ua[mi][3], addr);
            }
#pragma unroll
            for (int ng = 0; ng < 4; ng++) {
                int n0 = wnCol + ng * 16;
                unsigned addr = bBase +
                    ((k0 + bLaneK) * BSTR + n0 + bLaneN) * 2;
                unsigned r0, r1, r2, r3;
                ldsm_x4_t(r0, r1, r2, r3, addr);
                unsigned b0[2] = { r0, r1 };
                unsigned b1[2] = { r2, r3 };
                mma_f16(acc[0][ng * 2 + 0], ua[0], b0);
                mma_f16(acc[1][ng * 2 + 0], ua[1], b0);
                mma_f16(acc[0][ng * 2 + 1], ua[0], b1);
                mma_f16(acc[1][ng * 2 + 1], ua[1], b1);
            }
        }
        if (c < 7) {
            int nb_ = buf ^ 1;
#pragma unroll
            for (int p = 0; p < 4; p++) {
                *(uint2*)&As[nb_][arow[p] * ASTR + akc[p]] = sa[p];
                *(uint2*)&Bs[nb_][brow[p] * BSTR + bnc[p]] = sb[p];
            }
        }
        __syncthreads();
    }

    // ---- epilogue 1: fp16 h1 stores ----
#pragma unroll
    for (int mi = 0; mi < 2; mi++) {
#pragma unroll
        for (int nj = 0; nj < 8; nj++) {
            int r0 = rowBase + wmRow + mi * 16 + (lane >> 2);
            int col = wnCol + nj * 8 + (lane & 3) * 2;
            if (r0 < M)
                *(__half2*)&g_h1h[r0 * 128 + col] = __floats2half2_rn(acc[mi][nj][0], acc[mi][nj][1]);
            if (r0 + 8 < M)
                *(__half2*)&g_h1h[(r0 + 8) * 128 + col] = __floats2half2_rn(acc[mi][nj][2], acc[mi][nj][3]);
        }
    }

    // ---- epilogue 2: fused attention scores ----
    float s_part[2][2][4], d_part[2][2][4];
#pragma unroll
    for (int mi = 0; mi < 2; mi++)
#pragma unroll
        for (int r = 0; r < 2; r++)
#pragma unroll
            for (int hh = 0; hh < 4; hh++) { s_part[mi][r][hh] = 0.f; d_part[mi][r][hh] = 0.f; }

#pragma unroll
    for (int mi = 0; mi < 2; mi++) {
#pragma unroll
        for (int nj = 0; nj < 8; nj++) {
            int hh = nj >> 1;
            int ch0 = wnCol + nj * 8 + (lane & 3) * 2;
            float as0 = att_s[ch0], as1 = att_s[ch0 + 1];
            float ad0 = att_d[ch0], ad1 = att_d[ch0 + 1];
            s_part[mi][0][hh] += acc[mi][nj][0] * as0 + acc[mi][nj][1] * as1;
            d_part[mi][0][hh] += acc[mi][nj][0] * ad0 + acc[mi][nj][1] * ad1;
            s_part[mi][1][hh] += acc[mi][nj][2] * as0 + acc[mi][nj][3] * as1;
            d_part[mi][1][hh] += acc[mi][nj][2] * ad0 + acc[mi][nj][3] * ad1;
        }
    }
#pragma unroll
    for (int mi = 0; mi < 2; mi++)
#pragma unroll
        for (int r = 0; r < 2; r++)
#pragma unroll
            for (int hh = 0; hh < 4; hh++) {
                float vs = s_part[mi][r][hh], vd = d_part[mi][r][hh];
                vs += __shfl_xor_sync(0xffffffffu, vs, 1);
                vs += __shfl_xor_sync(0xffffffffu, vs, 2);
                vd += __shfl_xor_sync(0xffffffffu, vd, 1);
                vd += __shfl_xor_sync(0xffffffffu, vd, 2);
                s_part[mi][r][hh] = vs;
                d_part[mi][r][hh] = vd;
            }
    if ((lane & 3) == 0) {
        int hbase = wnCol >> 4;
#pragma unroll
        for (int mi = 0; mi < 2; mi++) {
            int r0 = rowBase + wmRow + mi * 16 + (lane >> 2);
#pragma unroll
            for (int r = 0; r < 2; r++) {
                int row = r0 + r * 8;
                if (row < M) {
#pragma unroll
                    for (int hh = 0; hh < 4; hh++) {
                        g_asrc1[row * 8 + hbase + hh] = s_part[mi][r][hh];
                        g_adst1[row * 8 + hbase + hh] = d_part[mi][r][hh];
                    }
                }
            }
        }
    }
}

// ---------------- layer1 gather: warp per node, 4-edge index batching --------
__global__ __launch_bounds__(256) void gather1_kernel(const float* __restrict__ bias) {
    int n = (blockIdx.x * blockDim.x + threadIdx.x) >> 5;
    int lane = threadIdx.x & 31;
    if (n >= N_NODES) return;
    int h = lane >> 2;
    float adv = g_adst1[n * 8 + h];
    int j = g_off[n], jend = g_off[n + 1];
    float4 acc = make_float4(0.f, 0.f, 0.f, 0.f);
    float dsum = 0.0f;
    for (; j + 3 < jend; j += 4) {
        int s0 = g_csr_src[j];
        int s1 = g_csr_src[j + 1];
        int s2 = g_csr_src[j + 2];
        int s3 = g_csr_src[j + 3];
        float a0 = g_asrc1[s0 * 8 + h];
        float a1 = g_asrc1[s1 * 8 + h];
        float a2 = g_asrc1[s2 * 8 + h];
        float a3 = g_asrc1[s3 * 8 + h];
        uint2 r0 = *(const uint2*)&g_h1h[s0 * 128 + lane * 4];
        uint2 r1 = *(const uint2*)&g_h1h[s1 * 128 + lane * 4];
        uint2 r2 = *(const uint2*)&g_h1h[s2 * 128 + lane * 4];
        uint2 r3 = *(const uint2*)&g_h1h[s3 * 128 + lane * 4];
        float e0 = __expf(lrelu(a0 + adv));
        float e1 = __expf(lrelu(a1 + adv));
        float e2 = __expf(lrelu(a2 + adv));
        float e3 = __expf(lrelu(a3 + adv));
        facc4(acc, r0, e0);
        facc4(acc, r1, e1);
        facc4(acc, r2, e2);
        facc4(acc, r3, e3);
        dsum += (e0 + e1) + (e2 + e3);
    }
    for (; j < jend; j++) {
        int sa = g_csr_src[j];
        float ea = __expf(lrelu(g_asrc1[sa * 8 + h] + adv));
        uint2 rw = *(const uint2*)&g_h1h[sa * 128 + lane * 4];
        facc4(acc, rw, ea);
        dsum += ea;
    }
    float inv = 1.0f / dsum;
    float4 b = *(const float4*)&bias[lane * 4];
    __half2 o01 = __floats2half2_rn(fmaxf(acc.x * inv + b.x, 0.0f),
                                    fmaxf(acc.y * inv + b.y, 0.0f));
    __half2 o23 = __floats2half2_rn(fmaxf(acc.z * inv + b.z, 0.0f),
                                    fmaxf(acc.w * inv + b.w, 0.0f));
    uint2 ov;
    ov.x = *(unsigned*)&o01;
    ov.y = *(unsigned*)&o23;
    *(uint2*)&g_hreluh[n * 128 + lane * 4] = ov;
}

// ---------------- GEMM2 (+ fused a_src2/a_dst2): h2 = hrelu @ W2 -------------
__global__ __launch_bounds__(256) void gemm2_kernel(const float* __restrict__ W2,
                                                    const float* __restrict__ att_s,
                                                    const float* __restrict__ att_d) {
    __shared__ float Ws[128 * 16];
    __shared__ float Hs[16][128];
    int tid = threadIdx.x;
    int base = blockIdx.x * 16;
    for (int i = tid; i < 128 * 16; i += 256) Ws[i] = W2[i];
    for (int i = tid; i < 16 * 128; i += 256) {
        int r = i >> 7, c = i & 127;
        int gr = base + r;
        Hs[r][c] = (gr < N_NODES) ? __half2float(g_hreluh[gr * 128 + c]) : 0.0f;
    }
    __syncthreads();
    int ty = tid >> 4, tx = tid & 15;
    float sum = 0.0f;
#pragma unroll 8
    for (int k = 0; k < 128; k++) sum += Hs[ty][k] * Ws[k * 16 + tx];
    float ss = sum * att_s[tx];
    float sd = sum * att_d[tx];
#pragma unroll
    for (int off = 8; off; off >>= 1) {
        ss += __shfl_xor_sync(0xffffffffu, ss, off);
        sd += __shfl_xor_sync(0xffffffffu, sd, off);
    }
    int row = base + ty;
    if (row < N_NODES) {
        g_h2h[row * 16 + tx] = __float2half_rn(sum);
        if (tx == 0) { g_asrc2[row] = ss; g_adst2[row] = sd; }
    }
}

// ---------------- layer2 gather: 4 lanes per node, 4-edge index batching -----
__global__ __launch_bounds__(256) void gather2_kernel(const float* __restrict__ bias,
                                                      float* __restrict__ out) {
    int gid = blockIdx.x * blockDim.x + threadIdx.x;
    int n = gid >> 2;
    int q = gid & 3;
    if (n >= N_NODES) return;
    float adv = g_adst2[n];
    int j = g_off[n], jend = g_off[n + 1];
    float4 acc = make_float4(0.f, 0.f, 0.f, 0.f);
    float dsum = 0.0f;
    for (; j + 3 < jend; j += 4) {
        int s0 = g_csr_src[j];
        int s1 = g_csr_src[j + 1];
        int s2 = g_csr_src[j + 2];
        int s3 = g_csr_src[j + 3];
        float a0 = g_asrc2[s0];
        float a1 = g_asrc2[s1];
        float a2 = g_asrc2[s2];
        float a3 = g_asrc2[s3];
        uint2 r0 = *(const uint2*)&g_h2h[s0 * 16 + q * 4];
        uint2 r1 = *(const uint2*)&g_h2h[s1 * 16 + q * 4];
        uint2 r2 = *(const uint2*)&g_h2h[s2 * 16 + q * 4];
        uint2 r3 = *(const uint2*)&g_h2h[s3 * 16 + q * 4];
        float e0 = __expf(lrelu(a0 + adv));
        float e1 = __expf(lrelu(a1 + adv));
        float e2 = __expf(lrelu(a2 + adv));
        float e3 = __expf(lrelu(a3 + adv));
        facc4(acc, r0, e0);
        facc4(acc, r1, e1);
        facc4(acc, r2, e2);
        facc4(acc, r3, e3);
        dsum += (e0 + e1) + (e2 + e3);
    }
    for (; j < jend; j++) {
        int sa = g_csr_src[j];
        float ea = __expf(lrelu(g_asrc2[sa] + adv));
        uint2 rw = *(const uint2*)&g_h2h[sa * 16 + q * 4];
        facc4(acc, rw, ea);
        dsum += ea;
    }
    float inv = 1.0f / dsum;
    float4 b = *(const float4*)&bias[q * 4];
    float4 v;
    v.x = acc.x * inv + b.x;
    v.y = acc.y * inv + b.y;
    v.z = acc.z * inv + b.z;
    v.w = acc.w * inv + b.w;
    *(float4*)&out[n * 16 + q * 4] = v;
}

// ---------------- launch: fork CSR chain || gemm1, join before gather1 -------
extern "C" void kernel_launch(void* const* d_in, const int* in_sizes, int n_in,
                              void* d_out, int out_size) {
    const float* x      = (const float*)d_in[0];
    const int*   ei     = (const int*)d_in[1];
    const float* W1     = (const float*)d_in[2];
    const float* att_s1 = (const float*)d_in[3];
    const float* att_d1 = (const float*)d_in[4];
    const float* b1     = (const float*)d_in[5];
    const float* W2     = (const float*)d_in[6];
    const float* att_s2 = (const float*)d_in[7];
    const float* att_d2 = (const float*)d_in[8];
    const float* b2     = (const float*)d_in[9];
    float* out = (float*)d_out;
    const int* src = ei;
    const int* dst = ei + N_EDGES;

    // Side stream + events for the independent CSR chain. Created fresh each
    // call (kernel_launch runs only a handful of times: correctness + capture);
    // not destroyed here because capture on stream 0 is still active. No
    // device memory is allocated by these calls.
    cudaStream_t s2;
    cudaEvent_t evFork, evJoin;
    cudaStreamCreateWithFlags(&s2, cudaStreamNonBlocking);
    cudaEventCreateWithFlags(&evFork, cudaEventDisableTiming);
    cudaEventCreateWithFlags(&evJoin, cudaEventDisableTiming);

    // fork: s2 joins the capture DAG after whatever precedes us on stream 0
    cudaEventRecord(evFork, 0);
    cudaStreamWaitEvent(s2, evFork, 0);

    // chain A (CSR build) on s2
    count_kernel<<<(E_TOT + 255) / 256, 256, 0, s2>>>(dst);
    scanA_kernel<<<NBLK_SCAN, 256, 0, s2>>>();
    scanC_kernel<<<NBLK_SCAN, 256, 0, s2>>>();
    scatter_kernel<<<(E_TOT + 255) / 256, 256, 0, s2>>>(src, dst);
    cudaEventRecord(evJoin, s2);

    // chain B (gemm1) on stream 0, concurrent with chain A
    gemm1_kernel<<<(N_NODES + 127) / 128, 256>>>(x, W1, att_s1, att_d1);

    // join: gather1 needs both CSR and h1/att scores
    cudaStreamWaitEvent(0, evJoin, 0);
    gather1_kernel<<<(N_NODES * 32 + 255) / 256, 256>>>(b1);
    gemm2_kernel<<<(N_NODES + 15) / 16, 256>>>(W2, att_s2, att_d2);
    gather2_kernel<<<(N_NODES * 4 + 255) / 256, 256>>>(b2, out);
}

// round 15
// speedup vs baseline: 1.9450x; 1.0004x over previous
#include <cuda_runtime.h>
#include <cuda_fp16.h>

#define N_NODES 50000
#define N_EDGES 1600000
#define E_TOT   (N_EDGES + N_NODES)
#define IN_C    256
#define HID_C   128
#define OUT_C   16
#define HEADS   8
#define NBLK_SCAN 49   // ceil(50000/1024)

// ---------------- scratch (device globals; zero-initialized at load) ---------
__device__ __align__(256) __half g_h1h[N_NODES * HID_C];     // fp16 messages L1
__device__ __align__(256) float  g_asrc1[N_NODES * HEADS];
__device__ __align__(256) float  g_adst1[N_NODES * HEADS];
__device__ __align__(256) __half g_hreluh[N_NODES * HID_C];  // fp16 layer1 out
__device__ __align__(256) __half g_h2h[N_NODES * OUT_C];     // fp16 messages L2
__device__ __align__(256) float  g_asrc2[N_NODES];
__device__ __align__(256) float  g_adst2[N_NODES];
__device__ __align__(256) int    g_deg[N_NODES];   // zeroed at end of scatter
__device__ __align__(256) int    g_off[N_NODES + 1];
__device__ __align__(256) int    g_rank[E_TOT];    // edge rank within its dst
__device__ __align__(256) int    g_part[64];
__device__ __align__(256) int    g_csr_src[E_TOT];

__device__ __forceinline__ float lrelu(float a) {
    return a > 0.0f ? a : 0.2f * a;
}

__device__ __forceinline__ void mma_f16(float* d, const unsigned* a, const unsigned* b) {
    asm volatile(
        "mma.sync.aligned.m16n8k16.row.col.f32.f16.f16.f32 "
        "{%0,%1,%2,%3}, {%4,%5,%6,%7}, {%8,%9}, {%0,%1,%2,%3};\n"
        : "+f"(d[0]), "+f"(d[1]), "+f"(d[2]), "+f"(d[3])
        : "r"(a[0]), "r"(a[1]), "r"(a[2]), "r"(a[3]), "r"(b[0]), "r"(b[1]));
}

__device__ __forceinline__ void ldsm_x4(unsigned& r0, unsigned& r1, unsigned& r2,
                                        unsigned& r3, unsigned addr) {
    asm volatile("ldmatrix.sync.aligned.m8n8.x4.shared.b16 {%0,%1,%2,%3}, [%4];"
                 : "=r"(r0), "=r"(r1), "=r"(r2), "=r"(r3) : "r"(addr));
}

__device__ __forceinline__ void ldsm_x4_t(unsigned& r0, unsigned& r1, unsigned& r2,
                                          unsigned& r3, unsigned addr) {
    asm volatile("ldmatrix.sync.aligned.m8n8.x4.trans.shared.b16 {%0,%1,%2,%3}, [%4];"
                 : "=r"(r0), "=r"(r1), "=r"(r2), "=r"(r3) : "r"(addr));
}

__device__ __forceinline__ uint2 f4_to_h4(float4 v) {
    __half2 lo = __floats2half2_rn(v.x, v.y);
    __half2 hi = __floats2half2_rn(v.z, v.w);
    uint2 r;
    r.x = *(unsigned*)&lo;
    r.y = *(unsigned*)&hi;
    return r;
}

// accumulate 4 fp16 channels (uint2) weighted by e into float4
__device__ __forceinline__ void facc4(float4& acc, uint2 rw, float e) {
    float2 f01 = __half22float2(*(__half2*)&rw.x);
    float2 f23 = __half22float2(*(__half2*)&rw.y);
    acc.x += f01.x * e;
    acc.y += f01.y * e;
    acc.z += f23.x * e;
    acc.w += f23.y * e;
}

// ---------------- CSR build ---------------------------------------------------
// count also records each edge's rank within its destination (atomic return).
__global__ void count_kernel(const int* __restrict__ dst) {
    int e = blockIdx.x * blockDim.x + threadIdx.x;
    if (e >= E_TOT) return;
    int d = (e < N_EDGES) ? dst[e] : e - N_EDGES;
    int r = atomicAdd(&g_deg[d], 1);
    g_rank[e] = r;
}

__global__ void scanA_kernel() {
    __shared__ int sh[8];
    int b = blockIdx.x, t = threadIdx.x;
    int base = b * 1024 + t * 4;
    int s = 0;
#pragma unroll
    for (int k = 0; k < 4; k++) { int i = base + k; if (i < N_NODES) s += g_deg[i]; }
#pragma unroll
    for (int o = 16; o; o >>= 1) s += __shfl_xor_sync(0xffffffffu, s, o);
    if ((t & 31) == 0) sh[t >> 5] = s;
    __syncthreads();
    if (t < 8) {
        int v = sh[t];
#pragma unroll
        for (int o = 4; o; o >>= 1) v += __shfl_xor_sync(0xffffffffu, v, o);
        if (t == 0) g_part[b] = v;
    }
}

__global__ void scanC_kernel() {
    __shared__ int ws[8];
    __shared__ int s_pre;
    int b = blockIdx.x, t = threadIdx.x;
    int lane = t & 31, w = t >> 5;
    if (w == 0) {
        int v = 0;
        if (lane < b && lane < NBLK_SCAN) v = g_part[lane];
        if (lane + 32 < b && lane + 32 < NBLK_SCAN) v += g_part[lane + 32];
#pragma unroll
        for (int o = 16; o; o >>= 1) v += __shfl_xor_sync(0xffffffffu, v, o);
        if (lane == 0) s_pre = v;
    }
    int base = b * 1024 + t * 4;
    int d0 = 0, d1 = 0, d2 = 0, d3 = 0;
    if (base + 0 < N_NODES) d0 = g_deg[base + 0];
    if (base + 1 < N_NODES) d1 = g_deg[base + 1];
    if (base + 2 < N_NODES) d2 = g_deg[base + 2];
    if (base + 3 < N_NODES) d3 = g_deg[base + 3];
    int tsum = d0 + d1 + d2 + d3;
    int v = tsum;
#pragma unroll
    for (int o = 1; o < 32; o <<= 1) {
        int u = __shfl_up_sync(0xffffffffu, v, o);
        if (lane >= o) v += u;
    }
    if (lane == 31) ws[w] = v;
    __syncthreads();
    int woff = 0;
    for (int i = 0; i < w; i++) woff += ws[i];
    int excl = v - tsum + woff + s_pre;
    int o0 = excl, o1 = o0 + d0, o2 = o1 + d1, o3 = o2 + d2;
    if (base + 0 < N_NODES) g_off[base + 0] = o0;
    if (base + 1 < N_NODES) g_off[base + 1] = o1;
    if (base + 2 < N_NODES) g_off[base + 2] = o2;
    if (base + 3 < N_NODES) g_off[base + 3] = o3;
    if (b == 0 && t == 0) g_off[N_NODES] = E_TOT;
}

// atomic-free scatter: position = off[d] + rank[e]
__global__ void scatter_kernel(const int* __restrict__ src, const int* __restrict__ dst) {
    int e = blockIdx.x * blockDim.x + threadIdx.x;
    if (e < E_TOT) {
        int s, d;
        if (e < N_EDGES) { s = src[e]; d = dst[e]; }
        else             { s = d = e - N_EDGES; }
        g_csr_src[g_off[d] + g_rank[e]] = s;
    }
    if (e < N_NODES) g_deg[e] = 0;   // reset for next invocation
}

// ---------------- GEMM1 (fp16 HMMA + ldmatrix) + fused att + fp16 h1 ---------
// BM=128 BN=64 BK=32, 256 threads (8 warps: 4x2), warp tile 32x32.
// grid = (391, 2): blockIdx.y selects the 64-col half. ~2 CTAs/SM.
#define ASTR 40
#define BSTR 72
__global__ __launch_bounds__(256) void gemm1_kernel(const float* __restrict__ A,
                                                    const float* __restrict__ B,
                                                    const float* __restrict__ att_s,
                                                    const float* __restrict__ att_d) {
    __shared__ __half As[2][128 * ASTR];
    __shared__ __half Bs[2][32 * BSTR];
    const int M = N_NODES;
    int rowBase = blockIdx.x * 128;
    int nBase = blockIdx.y * 64;
    int tid = threadIdx.x;
    int lane = tid & 31;
    int warpId = tid >> 5;
    int wmRow = (warpId >> 1) * 32;
    int wnCol = (warpId & 1) * 32;

    // A: 1024 float4/chunk (4/thread); B: 512 float4/chunk (2/thread)
    int arow[4], akc[4], brow[2], bnc[2];
#pragma unroll
    for (int p = 0; p < 4; p++) {
        int fidx = tid + p * 256;
        arow[p] = fidx >> 3;
        akc[p] = (fidx & 7) * 4;
    }
#pragma unroll
    for (int p = 0; p < 2; p++) {
        int fidx = tid + p * 256;
        brow[p] = fidx >> 4;               // 32 k-rows, 16 float4/row
        bnc[p] = (fidx & 15) * 4;
    }

    float acc[2][4][4];
#pragma unroll
    for (int i = 0; i < 2; i++)
#pragma unroll
        for (int j = 0; j < 4; j++)
#pragma unroll
            for (int q = 0; q < 4; q++) acc[i][j][q] = 0.0f;

    unsigned aShared0 = (unsigned)__cvta_generic_to_shared(&As[0][0]);
    unsigned bShared0 = (unsigned)__cvta_generic_to_shared(&Bs[0][0]);
    unsigned aBufBytes = 128 * ASTR * 2;
    unsigned bBufBytes = 32 * BSTR * 2;
    int aLaneRow = lane & 15;
    int aLaneK = ((lane >> 4) & 1) * 8;
    int bLaneK = lane & 15;
    int bLaneN = ((lane >> 4) & 1) * 8;

    // ---- prologue: chunk 0 ----
#pragma unroll
    for (int p = 0; p < 4; p++) {
        int gr = rowBase + arow[p];
        float4 av = make_float4(0.f, 0.f, 0.f, 0.f);
        if (gr < M) av = *(const float4*)&A[(long)gr * IN_C + akc[p]];
        *(uint2*)&As[0][arow[p] * ASTR + akc[p]] = f4_to_h4(av);
    }
#pragma unroll
    for (int p = 0; p < 2; p++) {
        float4 bv = *(const float4*)&B[brow[p] * 128 + nBase + bnc[p]];
        *(uint2*)&Bs[0][brow[p] * BSTR + bnc[p]] = f4_to_h4(bv);
    }
    __syncthreads();

    uint2 sa[4], sb[2];
    for (int c = 0; c < 8; c++) {
        int buf = c & 1;
        if (c < 7) {
            int kbase = (c + 1) * 32;
#pragma unroll
            for (int p = 0; p < 4; p++) {
                int gr = rowBase + arow[p];
                float4 av = make_float4(0.f, 0.f, 0.f, 0.f);
                if (gr < M) av = *(const float4*)&A[(long)gr * IN_C + kbase + akc[p]];
                sa[p] = f4_to_h4(av);
            }
#pragma unroll
            for (int p = 0; p < 2; p++) {
                float4 bv = *(const float4*)&B[(kbase + brow[p]) * 128 + nBase + bnc[p]];
                sb[p] = f4_to_h4(bv);
            }
        }
        unsigned aBase = aShared0 + buf * aBufBytes;
        unsigned bBase = bShared0 + buf * bBufBytes;
#pragma unroll
        for (int ks = 0; ks < 2; ks++) {
            int k0 = ks * 16;
            unsigned ua[2][4];
#pragma unroll
            for (int mi = 0; mi < 2; mi++) {
                unsigned addr = aBase +
                    ((wmRow + mi * 16 + aLaneRow) * ASTR + k0 + aLaneK) * 2;
                ldsm_x4(ua[mi][0], ua[mi][1], ua[mi][2], ua[mi][3], addr);
            }
#pragma unroll
            for (int ng = 0; ng < 2; ng++) {
                int n0 = wnCol + ng * 16;
                unsigned addr = bBase +
                    ((k0 + bLaneK) * BSTR + n0 + bLaneN) * 2;
                unsigned r0, r1, r2, r3;
                ldsm_x4_t(r0, r1, r2, r3, addr);
                unsigned b0[2] = { r0, r1 };
                unsigned b1[2] = { r2, r3 };
                mma_f16(acc[0][ng * 2 + 0], ua[0], b0);
                mma_f16(acc[1][ng * 2 + 0], ua[1], b0);
                mma_f16(acc[0][ng * 2 + 1], ua[0], b1);
                mma_f16(acc[1][ng * 2 + 1], ua[1], b1);
            }
        }
        if (c < 7) {
            int nb_ = buf ^ 1;
#pragma unroll
            for (int p = 0; p < 4; p++)
                *(uint2*)&As[nb_][arow[p] * ASTR + akc[p]] = sa[p];
#pragma unroll
            for (int p = 0; p < 2; p++)
                *(uint2*)&Bs[nb_][brow[p] * BSTR + bnc[p]] = sb[p];
        }
        __syncthreads();
    }

    // ---- epilogue 1: fp16 h1 stores ----
#pragma unroll
    for (int mi = 0; mi < 2; mi++) {
#pragma unroll
        for (int nj = 0; nj < 4; nj++) {
            int r0 = rowBase + wmRow + mi * 16 + (lane >> 2);
            int col = nBase + wnCol + nj * 8 + (lane & 3) * 2;
            if (r0 < M)
                *(__half2*)&g_h1h[r0 * 128 + col] = __floats2half2_rn(acc[mi][nj][0], acc[mi][nj][1]);
            if (r0 + 8 < M)
                *(__half2*)&g_h1h[(r0 + 8) * 128 + col] = __floats2half2_rn(acc[mi][nj][2], acc[mi][nj][3]);
        }
    }

    // ---- epilogue 2: fused attention scores (warp covers 2 heads) ----
    float s_part[2][2][2], d_part[2][2][2];
#pragma unroll
    for (int mi = 0; mi < 2; mi++)
#pragma unroll
        for (int r = 0; r < 2; r++)
#pragma unroll
            for (int hh = 0; hh < 2; hh++) { s_part[mi][r][hh] = 0.f; d_part[mi][r][hh] = 0.f; }

#pragma unroll
    for (int mi = 0; mi < 2; mi++) {
#pragma unroll
        for (int nj = 0; nj < 4; nj++) {
            int hh = nj >> 1;
            int ch0 = nBase + wnCol + nj * 8 + (lane & 3) * 2;
            float as0 = att_s[ch0], as1 = att_s[ch0 + 1];
            float ad0 = att_d[ch0], ad1 = att_d[ch0 + 1];
            s_part[mi][0][hh] += acc[mi][nj][0] * as0 + acc[mi][nj][1] * as1;
            d_part[mi][0][hh] += acc[mi][nj][0] * ad0 + acc[mi][nj][1] * ad1;
            s_part[mi][1][hh] += acc[mi][nj][2] * as0 + acc[mi][nj][3] * as1;
            d_part[mi][1][hh] += acc[mi][nj][2] * ad0 + acc[mi][nj][3] * ad1;
        }
    }
#pragma unroll
    for (int mi = 0; mi < 2; mi++)
#pragma unroll
        for (int r = 0; r < 2; r++)
#pragma unroll
            for (int hh = 0; hh < 2; hh++) {
                float vs = s_part[mi][r][hh], vd = d_part[mi][r][hh];
                vs += __shfl_xor_sync(0xffffffffu, vs, 1);
                vs += __shfl_xor_sync(0xffffffffu, vs, 2);
                vd += __shfl_xor_sync(0xffffffffu, vd, 1);
                vd += __shfl_xor_sync(0xffffffffu, vd, 2);
                s_part[mi][r][hh] = vs;
                d_part[mi][r][hh] = vd;
            }
    if ((lane & 3) == 0) {
        int hbase = (nBase + wnCol) >> 4;
#pragma unroll
        for (int mi = 0; mi < 2; mi++) {
            int r0 = rowBase + wmRow + mi * 16 + (lane >> 2);
#pragma unroll
            for (int r = 0; r < 2; r++) {
                int row = r0 + r * 8;
                if (row < M) {
#pragma unroll
                    for (int hh = 0; hh < 2; hh++) {
                        g_asrc1[row * 8 + hbase + hh] = s_part[mi][r][hh];
                        g_adst1[row * 8 + hbase + hh] = d_part[mi][r][hh];
                    }
                }
            }
        }
    }
}

// ---------------- layer1 gather: warp per node, 4-edge index batching --------
__global__ __launch_bounds__(256) void gather1_kernel(const float* __restrict__ bias) {
    int n = (blockIdx.x * blockDim.x + threadIdx.x) >> 5;
    int lane = threadIdx.x & 31;
    if (n >= N_NODES) return;
    int h = lane >> 2;
    float adv = g_adst1[n * 8 + h];
    int j = g_off[n], jend = g_off[n + 1];
    float4 acc = make_float4(0.f, 0.f, 0.f, 0.f);
    float dsum = 0.0f;
    for (; j + 3 < jend; j += 4) {
        int s0 = g_csr_src[j];
        int s1 = g_csr_src[j + 1];
        int s2 = g_csr_src[j + 2];
        int s3 = g_csr_src[j + 3];
        float a0 = g_asrc1[s0 * 8 + h];
        float a1 = g_asrc1[s1 * 8 + h];
        float a2 = g_asrc1[s2 * 8 + h];
        float a3 = g_asrc1[s3 * 8 + h];
        uint2 r0 = *(const uint2*)&g_h1h[s0 * 128 + lane * 4];
        uint2 r1 = *(const uint2*)&g_h1h[s1 * 128 + lane * 4];
        uint2 r2 = *(const uint2*)&g_h1h[s2 * 128 + lane * 4];
        uint2 r3 = *(const uint2*)&g_h1h[s3 * 128 + lane * 4];
        float e0 = __expf(lrelu(a0 + adv));
        float e1 = __expf(lrelu(a1 + adv));
        float e2 = __expf(lrelu(a2 + adv));
        float e3 = __expf(lrelu(a3 + adv));
        facc4(acc, r0, e0);
        facc4(acc, r1, e1);
        facc4(acc, r2, e2);
        facc4(acc, r3, e3);
        dsum += (e0 + e1) + (e2 + e3);
    }
    for (; j < jend; j++) {
        int sa = g_csr_src[j];
        float ea = __expf(lrelu(g_asrc1[sa * 8 + h] + adv));
        uint2 rw = *(const uint2*)&g_h1h[sa * 128 + lane * 4];
        facc4(acc, rw, ea);
        dsum += ea;
    }
    float inv = 1.0f / dsum;
    float4 b = *(const float4*)&bias[lane * 4];
    __half2 o01 = __floats2half2_rn(fmaxf(acc.x * inv + b.x, 0.0f),
                                    fmaxf(acc.y * inv + b.y, 0.0f));
    __half2 o23 = __floats2half2_rn(fmaxf(acc.z * inv + b.z, 0.0f),
                                    fmaxf(acc.w * inv + b.w, 0.0f));
    uint2 ov;
    ov.x = *(unsigned*)&o01;
    ov.y = *(unsigned*)&o23;
    *(uint2*)&g_hreluh[n * 128 + lane * 4] = ov;
}

// ---------------- GEMM2 (+ fused a_src2/a_dst2): h2 = hrelu @ W2 -------------
__global__ __launch_bounds__(256) void gemm2_kernel(const float* __restrict__ W2,
                                                    const float* __restrict__ att_s,
                                                    const float* __restrict__ att_d) {
    __shared__ float Ws[128 * 16];
    __shared__ float Hs[16][128];
    int tid = threadIdx.x;
    int base = blockIdx.x * 16;
    for (int i = tid; i < 128 * 16; i += 256) Ws[i] = W2[i];
    for (int i = tid; i < 16 * 128; i += 256) {
        int r = i >> 7, c = i & 127;
        int gr = base + r;
        Hs[r][c] = (gr < N_NODES) ? __half2float(g_hreluh[gr * 128 + c]) : 0.0f;
    }
    __syncthreads();
    int ty = tid >> 4, tx = tid & 15;
    float sum = 0.0f;
#pragma unroll 8
    for (int k = 0; k < 128; k++) sum += Hs[ty][k] * Ws[k * 16 + tx];
    float ss = sum * att_s[tx];
    float sd = sum * att_d[tx];
#pragma unroll
    for (int off = 8; off; off >>= 1) {
        ss += __shfl_xor_sync(0xffffffffu, ss, off);
        sd += __shfl_xor_sync(0xffffffffu, sd, off);
    }
    int row = base + ty;
    if (row < N_NODES) {
        g_h2h[row * 16 + tx] = __float2half_rn(sum);
        if (tx == 0) { g_asrc2[row] = ss; g_adst2[row] = sd; }
    }
}

// ---------------- layer2 gather: 4 lanes per node, 4-edge index batching -----
__global__ __launch_bounds__(256) void gather2_kernel(const float* __restrict__ bias,
                                                      float* __restrict__ out) {
    int gid = blockIdx.x * blockDim.x + threadIdx.x;
    int n = gid >> 2;
    int q = gid & 3;
    if (n >= N_NODES) return;
    float adv = g_adst2[n];
    int j = g_off[n], jend = g_off[n + 1];
    float4 acc = make_float4(0.f, 0.f, 0.f, 0.f);
    float dsum = 0.0f;
    for (; j + 3 < jend; j += 4) {
        int s0 = g_csr_src[j];
        int s1 = g_csr_src[j + 1];
        int s2 = g_csr_src[j + 2];
        int s3 = g_csr_src[j + 3];
        float a0 = g_asrc2[s0];
        float a1 = g_asrc2[s1];
        float a2 = g_asrc2[s2];
        float a3 = g_asrc2[s3];
        uint2 r0 = *(const uint2*)&g_h2h[s0 * 16 + q * 4];
        uint2 r1 = *(const uint2*)&g_h2h[s1 * 16 + q * 4];
        uint2 r2 = *(const uint2*)&g_h2h[s2 * 16 + q * 4];
        uint2 r3 = *(const uint2*)&g_h2h[s3 * 16 + q * 4];
        float e0 = __expf(lrelu(a0 + adv));
        float e1 = __expf(lrelu(a1 + adv));
        float e2 = __expf(lrelu(a2 + adv));
        float e3 = __expf(lrelu(a3 + adv));
        facc4(acc, r0, e0);
        facc4(acc, r1, e1);
        facc4(acc, r2, e2);
        facc4(acc, r3, e3);
        dsum += (e0 + e1) + (e2 + e3);
    }
    for (; j < jend; j++) {
        int sa = g_csr_src[j];
        float ea = __expf(lrelu(g_asrc2[sa] + adv));
        uint2 rw = *(const uint2*)&g_h2h[sa * 16 + q * 4];
        facc4(acc, rw, ea);
        dsum += ea;
    }
    float inv = 1.0f / dsum;
    float4 b = *(const float4*)&bias[q * 4];
    float4 v;
    v.x = acc.x * inv + b.x;
    v.y = acc.y * inv + b.y;
    v.z = acc.z * inv + b.z;
    v.w = acc.w * inv + b.w;
    *(float4*)&out[n * 16 + q * 4] = v;
}

// ---------------- launch: fork CSR chain || gemm1, join before gather1 -------
extern "C" void kernel_launch(void* const* d_in, const int* in_sizes, int n_in,
                              void* d_out, int out_size) {
    const float* x      = (const float*)d_in[0];
    const int*   ei     = (const int*)d_in[1];
    const float* W1     = (const float*)d_in[2];
    const float* att_s1 = (const float*)d_in[3];
    const float* att_d1 = (const float*)d_in[4];
    const float* b1     = (const float*)d_in[5];
    const float* W2     = (const float*)d_in[6];
    const float* att_s2 = (const float*)d_in[7];
    const float* att_d2 = (const float*)d_in[8];
    const float* b2     = (const float*)d_in[9];
    float* out = (float*)d_out;
    const int* src = ei;
    const int* dst = ei + N_EDGES;

    cudaStream_t s2;
    cudaEvent_t evFork, evJoin;
    cudaStreamCreateWithFlags(&s2, cudaStreamNonBlocking);
    cudaEventCreateWithFlags(&evFork, cudaEventDisableTiming);
    cudaEventCreateWithFlags(&evJoin, cudaEventDisableTiming);

    // fork
    cudaEventRecord(evFork, 0);
    cudaStreamWaitEvent(s2, evFork, 0);

    // chain A (CSR build) on s2
    count_kernel<<<(E_TOT + 255) / 256, 256, 0, s2>>>(dst);
    scanA_kernel<<<NBLK_SCAN, 256, 0, s2>>>();
    scanC_kernel<<<NBLK_SCAN, 256, 0, s2>>>();
    scatter_kernel<<<(E_TOT + 255) / 256, 256, 0, s2>>>(src, dst);
    cudaEventRecord(evJoin, s2);

    // chain B (gemm1) on stream 0, concurrent with chain A
    dim3 g1grid((N_NODES + 127) / 128, 2);
    gemm1_kernel<<<g1grid, 256>>>(x, W1, att_s1, att_d1);

    // join: gather1 needs both CSR and h1/att scores
    cudaStreamWaitEvent(0, evJoin, 0);
    gather1_kernel<<<(N_NODES * 32 + 255) / 256, 256>>>(b1);
    gemm2_kernel<<<(N_NODES + 15) / 16, 256>>>(W2, att_s2, att_d2);
    gather2_kernel<<<(N_NODES * 4 + 255) / 256, 256>>>(b2, out);
}

// round 16
// speedup vs baseline: 1.9581x; 1.0068x over previous
#include <cuda_runtime.h>
#include <cuda_fp16.h>

#define N_NODES 50000
#define N_EDGES 1600000
#define E_TOT   (N_EDGES + N_NODES)
#define IN_C    256
#define HID_C   128
#define OUT_C   16
#define HEADS   8
#define NBLK_SCAN 49   // ceil(50000/1024)

// ---------------- scratch (device globals; zero-initialized at load) ---------
__device__ __align__(256) __half g_h1h[N_NODES * HID_C];     // fp16 messages L1
__device__ __align__(256) float  g_asrc1[N_NODES * HEADS];
__device__ __align__(256) float  g_adst1[N_NODES * HEADS];
__device__ __align__(256) __half g_hreluh[N_NODES * HID_C];  // fp16 layer1 out
__device__ __align__(256) __half g_h2h[N_NODES * OUT_C];     // fp16 messages L2
__device__ __align__(256) float  g_asrc2[N_NODES];
__device__ __align__(256) float  g_adst2[N_NODES];
__device__ __align__(256) int    g_deg[N_NODES];   // zeroed at end of scatter
__device__ __align__(256) int    g_off[N_NODES + 1];
__device__ __align__(256) int    g_rank[E_TOT];    // edge rank within its dst
__device__ __align__(256) int    g_part[64];
__device__ __align__(256) int    g_csr_src[E_TOT];

__device__ __forceinline__ float lrelu(float a) {
    return a > 0.0f ? a : 0.2f * a;
}

__device__ __forceinline__ void mma_f16(float* d, const unsigned* a, const unsigned* b) {
    asm volatile(
        "mma.sync.aligned.m16n8k16.row.col.f32.f16.f16.f32 "
        "{%0,%1,%2,%3}, {%4,%5,%6,%7}, {%8,%9}, {%0,%1,%2,%3};\n"
        : "+f"(d[0]), "+f"(d[1]), "+f"(d[2]), "+f"(d[3])
        : "r"(a[0]), "r"(a[1]), "r"(a[2]), "r"(a[3]), "r"(b[0]), "r"(b[1]));
}

__device__ __forceinline__ void ldsm_x4(unsigned& r0, unsigned& r1, unsigned& r2,
                                        unsigned& r3, unsigned addr) {
    asm volatile("ldmatrix.sync.aligned.m8n8.x4.shared.b16 {%0,%1,%2,%3}, [%4];"
                 : "=r"(r0), "=r"(r1), "=r"(r2), "=r"(r3) : "r"(addr));
}

__device__ __forceinline__ void ldsm_x4_t(unsigned& r0, unsigned& r1, unsigned& r2,
                                          unsigned& r3, unsigned addr) {
    asm volatile("ldmatrix.sync.aligned.m8n8.x4.trans.shared.b16 {%0,%1,%2,%3}, [%4];"
                 : "=r"(r0), "=r"(r1), "=r"(r2), "=r"(r3) : "r"(addr));
}

__device__ __forceinline__ uint2 f4_to_h4(float4 v) {
    __half2 lo = __floats2half2_rn(v.x, v.y);
    __half2 hi = __floats2half2_rn(v.z, v.w);
    uint2 r;
    r.x = *(unsigned*)&lo;
    r.y = *(unsigned*)&hi;
    return r;
}

// accumulate 4 fp16 channels (uint2) weighted by e into float4
__device__ __forceinline__ void facc4(float4& acc, uint2 rw, float e) {
    float2 f01 = __half22float2(*(__half2*)&rw.x);
    float2 f23 = __half22float2(*(__half2*)&rw.y);
    acc.x += f01.x * e;
    acc.y += f01.y * e;
    acc.z += f23.x * e;
    acc.w += f23.y * e;
}

// ---------------- CSR build ---------------------------------------------------
__global__ void count_kernel(const int* __restrict__ dst) {
    int e = blockIdx.x * blockDim.x + threadIdx.x;
    if (e >= E_TOT) return;
    int d = (e < N_EDGES) ? dst[e] : e - N_EDGES;
    int r = atomicAdd(&g_deg[d], 1);
    g_rank[e] = r;
}

__global__ void scanA_kernel() {
    __shared__ int sh[8];
    int b = blockIdx.x, t = threadIdx.x;
    int base = b * 1024 + t * 4;
    int s = 0;
#pragma unroll
    for (int k = 0; k < 4; k++) { int i = base + k; if (i < N_NODES) s += g_deg[i]; }
#pragma unroll
    for (int o = 16; o; o >>= 1) s += __shfl_xor_sync(0xffffffffu, s, o);
    if ((t & 31) == 0) sh[t >> 5] = s;
    __syncthreads();
    if (t < 8) {
        int v = sh[t];
#pragma unroll
        for (int o = 4; o; o >>= 1) v += __shfl_xor_sync(0xffffffffu, v, o);
        if (t == 0) g_part[b] = v;
    }
}

__global__ void scanC_kernel() {
    __shared__ int ws[8];
    __shared__ int s_pre;
    int b = blockIdx.x, t = threadIdx.x;
    int lane = t & 31, w = t >> 5;
    if (w == 0) {
        int v = 0;
        if (lane < b && lane < NBLK_SCAN) v = g_part[lane];
        if (lane + 32 < b && lane + 32 < NBLK_SCAN) v += g_part[lane + 32];
#pragma unroll
        for (int o = 16; o; o >>= 1) v += __shfl_xor_sync(0xffffffffu, v, o);
        if (lane == 0) s_pre = v;
    }
    int base = b * 1024 + t * 4;
    int d0 = 0, d1 = 0, d2 = 0, d3 = 0;
    if (base + 0 < N_NODES) d0 = g_deg[base + 0];
    if (base + 1 < N_NODES) d1 = g_deg[base + 1];
    if (base + 2 < N_NODES) d2 = g_deg[base + 2];
    if (base + 3 < N_NODES) d3 = g_deg[base + 3];
    int tsum = d0 + d1 + d2 + d3;
    int v = tsum;
#pragma unroll
    for (int o = 1; o < 32; o <<= 1) {
        int u = __shfl_up_sync(0xffffffffu, v, o);
        if (lane >= o) v += u;
    }
    if (lane == 31) ws[w] = v;
    __syncthreads();
    int woff = 0;
    for (int i = 0; i < w; i++) woff += ws[i];
    int excl = v - tsum + woff + s_pre;
    int o0 = excl, o1 = o0 + d0, o2 = o1 + d1, o3 = o2 + d2;
    if (base + 0 < N_NODES) g_off[base + 0] = o0;
    if (base + 1 < N_NODES) g_off[base + 1] = o1;
    if (base + 2 < N_NODES) g_off[base + 2] = o2;
    if (base + 3 < N_NODES) g_off[base + 3] = o3;
    if (b == 0 && t == 0) g_off[N_NODES] = E_TOT;
}

// atomic-free scatter: position = off[d] + rank[e]
__global__ void scatter_kernel(const int* __restrict__ src, const int* __restrict__ dst) {
    int e = blockIdx.x * blockDim.x + threadIdx.x;
    if (e < E_TOT) {
        int s, d;
        if (e < N_EDGES) { s = src[e]; d = dst[e]; }
        else             { s = d = e - N_EDGES; }
        g_csr_src[g_off[d] + g_rank[e]] = s;
    }
    if (e < N_NODES) g_deg[e] = 0;   // reset for next invocation
}

// ---------------- GEMM1 (fp16 HMMA + ldmatrix) + fused att + fp16 h1 ---------
// BM=128 BN=64 BK=32, 256 threads (8 warps: 4x2), warp tile 32x32.
// __launch_bounds__(256, 2): cap regs at 128 -> 2 CTAs/SM.
#define ASTR 40
#define BSTR 72
__global__ __launch_bounds__(256, 2) void gemm1_kernel(const float* __restrict__ A,
                                                       const float* __restrict__ B,
                                                       const float* __restrict__ att_s,
                                                       const float* __restrict__ att_d) {
    __shared__ __half As[2][128 * ASTR];
    __shared__ __half Bs[2][32 * BSTR];
    const int M = N_NODES;
    int rowBase = blockIdx.x * 128;
    int nBase = blockIdx.y * 64;
    int tid = threadIdx.x;
    int lane = tid & 31;
    int warpId = tid >> 5;
    int wmRow = (warpId >> 1) * 32;
    int wnCol = (warpId & 1) * 32;

    int arow[4], akc[4], brow[2], bnc[2];
#pragma unroll
    for (int p = 0; p < 4; p++) {
        int fidx = tid + p * 256;
        arow[p] = fidx >> 3;
        akc[p] = (fidx & 7) * 4;
    }
#pragma unroll
    for (int p = 0; p < 2; p++) {
        int fidx = tid + p * 256;
        brow[p] = fidx >> 4;
        bnc[p] = (fidx & 15) * 4;
    }

    float acc[2][4][4];
#pragma unroll
    for (int i = 0; i < 2; i++)
#pragma unroll
        for (int j = 0; j < 4; j++)
#pragma unroll
            for (int q = 0; q < 4; q++) acc[i][j][q] = 0.0f;

    unsigned aShared0 = (unsigned)__cvta_generic_to_shared(&As[0][0]);
    unsigned bShared0 = (unsigned)__cvta_generic_to_shared(&Bs[0][0]);
    unsigned aBufBytes = 128 * ASTR * 2;
    unsigned bBufBytes = 32 * BSTR * 2;
    int aLaneRow = lane & 15;
    int aLaneK = ((lane >> 4) & 1) * 8;
    int bLaneK = lane & 15;
    int bLaneN = ((lane >> 4) & 1) * 8;

#pragma unroll
    for (int p = 0; p < 4; p++) {
        int gr = rowBase + arow[p];
        float4 av = make_float4(0.f, 0.f, 0.f, 0.f);
        if (gr < M) av = *(const float4*)&A[(long)gr * IN_C + akc[p]];
        *(uint2*)&As[0][arow[p] * ASTR + akc[p]] = f4_to_h4(av);
    }
#pragma unroll
    for (int p = 0; p < 2; p++) {
        float4 bv = *(const float4*)&B[brow[p] * 128 + nBase + bnc[p]];
        *(uint2*)&Bs[0][brow[p] * BSTR + bnc[p]] = f4_to_h4(bv);
    }
    __syncthreads();

    uint2 sa[4], sb[2];
    for (int c = 0; c < 8; c++) {
        int buf = c & 1;
        if (c < 7) {
            int kbase = (c + 1) * 32;
#pragma unroll
            for (int p = 0; p < 4; p++) {
                int gr = rowBase + arow[p];
                float4 av = make_float4(0.f, 0.f, 0.f, 0.f);
                if (gr < M) av = *(const float4*)&A[(long)gr * IN_C + kbase + akc[p]];
                sa[p] = f4_to_h4(av);
            }
#pragma unroll
            for (int p = 0; p < 2; p++) {
                float4 bv = *(const float4*)&B[(kbase + brow[p]) * 128 + nBase + bnc[p]];
                sb[p] = f4_to_h4(bv);
            }
        }
        unsigned aBase = aShared0 + buf * aBufBytes;
        unsigned bBase = bShared0 + buf * bBufBytes;
#pragma unroll
        for (int ks = 0; ks < 2; ks++) {
            int k0 = ks * 16;
            unsigned ua[2][4];
#pragma unroll
            for (int mi = 0; mi < 2; mi++) {
                unsigned addr = aBase +
                    ((wmRow + mi * 16 + aLaneRow) * ASTR + k0 + aLaneK) * 2;
                ldsm_x4(ua[mi][0], ua[mi][1], ua[mi][2], ua[mi][3], addr);
            }
#pragma unroll
            for (int ng = 0; ng < 2; ng++) {
                int n0 = wnCol + ng * 16;
                unsigned addr = bBase +
                    ((k0 + bLaneK) * BSTR + n0 + bLaneN) * 2;
                unsigned r0, r1, r2, r3;
                ldsm_x4_t(r0, r1, r2, r3, addr);
                unsigned b0[2] = { r0, r1 };
                unsigned b1[2] = { r2, r3 };
                mma_f16(acc[0][ng * 2 + 0], ua[0], b0);
                mma_f16(acc[1][ng * 2 + 0], ua[1], b0);
                mma_f16(acc[0][ng * 2 + 1], ua[0], b1);
                mma_f16(acc[1][ng * 2 + 1], ua[1], b1);
            }
        }
        if (c < 7) {
            int nb_ = buf ^ 1;
#pragma unroll
            for (int p = 0; p < 4; p++)
                *(uint2*)&As[nb_][arow[p] * ASTR + akc[p]] = sa[p];
#pragma unroll
            for (int p = 0; p < 2; p++)
                *(uint2*)&Bs[nb_][brow[p] * BSTR + bnc[p]] = sb[p];
        }
        __syncthreads();
    }

    // ---- epilogue 1: fp16 h1 stores ----
#pragma unroll
    for (int mi = 0; mi < 2; mi++) {
#pragma unroll
        for (int nj = 0; nj < 4; nj++) {
            int r0 = rowBase + wmRow + mi * 16 + (lane >> 2);
            int col = nBase + wnCol + nj * 8 + (lane & 3) * 2;
            if (r0 < M)
                *(__half2*)&g_h1h[r0 * 128 + col] = __floats2half2_rn(acc[mi][nj][0], acc[mi][nj][1]);
            if (r0 + 8 < M)
                *(__half2*)&g_h1h[(r0 + 8) * 128 + col] = __floats2half2_rn(acc[mi][nj][2], acc[mi][nj][3]);
        }
    }

    // ---- epilogue 2: fused attention scores (warp covers 2 heads) ----
    float s_part[2][2][2], d_part[2][2][2];
#pragma unroll
    for (int mi = 0; mi < 2; mi++)
#pragma unroll
        for (int r = 0; r < 2; r++)
#pragma unroll
            for (int hh = 0; hh < 2; hh++) { s_part[mi][r][hh] = 0.f; d_part[mi][r][hh] = 0.f; }

#pragma unroll
    for (int mi = 0; mi < 2; mi++) {
#pragma unroll
        for (int nj = 0; nj < 4; nj++) {
            int hh = nj >> 1;
            int ch0 = nBase + wnCol + nj * 8 + (lane & 3) * 2;
            float as0 = att_s[ch0], as1 = att_s[ch0 + 1];
            float ad0 = att_d[ch0], ad1 = att_d[ch0 + 1];
            s_part[mi][0][hh] += acc[mi][nj][0] * as0 + acc[mi][nj][1] * as1;
            d_part[mi][0][hh] += acc[mi][nj][0] * ad0 + acc[mi][nj][1] * ad1;
            s_part[mi][1][hh] += acc[mi][nj][2] * as0 + acc[mi][nj][3] * as1;
            d_part[mi][1][hh] += acc[mi][nj][2] * ad0 + acc[mi][nj][3] * ad1;
        }
    }
#pragma unroll
    for (int mi = 0; mi < 2; mi++)
#pragma unroll
        for (int r = 0; r < 2; r++)
#pragma unroll
            for (int hh = 0; hh < 2; hh++) {
                float vs = s_part[mi][r][hh], vd = d_part[mi][r][hh];
                vs += __shfl_xor_sync(0xffffffffu, vs, 1);
                vs += __shfl_xor_sync(0xffffffffu, vs, 2);
                vd += __shfl_xor_sync(0xffffffffu, vd, 1);
                vd += __shfl_xor_sync(0xffffffffu, vd, 2);
                s_part[mi][r][hh] = vs;
                d_part[mi][r][hh] = vd;
            }
    if ((lane & 3) == 0) {
        int hbase = (nBase + wnCol) >> 4;
#pragma unroll
        for (int mi = 0; mi < 2; mi++) {
            int r0 = rowBase + wmRow + mi * 16 + (lane >> 2);
#pragma unroll
            for (int r = 0; r < 2; r++) {
                int row = r0 + r * 8;
                if (row < M) {
#pragma unroll
                    for (int hh = 0; hh < 2; hh++) {
                        g_asrc1[row * 8 + hbase + hh] = s_part[mi][r][hh];
                        g_adst1[row * 8 + hbase + hh] = d_part[mi][r][hh];
                    }
                }
            }
        }
    }
}

// ---------------- layer1 gather: warp per node, 8-edge index batching --------
__global__ __launch_bounds__(256) void gather1_kernel(const float* __restrict__ bias) {
    int n = (blockIdx.x * blockDim.x + threadIdx.x) >> 5;
    int lane = threadIdx.x & 31;
    if (n >= N_NODES) return;
    int h = lane >> 2;
    float adv = g_adst1[n * 8 + h];
    int j = g_off[n], jend = g_off[n + 1];
    float4 acc = make_float4(0.f, 0.f, 0.f, 0.f);
    float dsum = 0.0f;
    for (; j + 7 < jend; j += 8) {
        int s[8];
#pragma unroll
        for (int k = 0; k < 8; k++) s[k] = g_csr_src[j + k];
        float a[8];
#pragma unroll
        for (int k = 0; k < 8; k++) a[k] = g_asrc1[s[k] * 8 + h];
        uint2 r[8];
#pragma unroll
        for (int k = 0; k < 8; k++) r[k] = *(const uint2*)&g_h1h[s[k] * 128 + lane * 4];
#pragma unroll
        for (int k = 0; k < 8; k++) {
            float e = __expf(lrelu(a[k] + adv));
            facc4(acc, r[k], e);
            dsum += e;
        }
    }
    for (; j < jend; j++) {
        int sa = g_csr_src[j];
        float ea = __expf(lrelu(g_asrc1[sa * 8 + h] + adv));
        uint2 rw = *(const uint2*)&g_h1h[sa * 128 + lane * 4];
        facc4(acc, rw, ea);
        dsum += ea;
    }
    float inv = 1.0f / dsum;
    float4 b = *(const float4*)&bias[lane * 4];
    __half2 o01 = __floats2half2_rn(fmaxf(acc.x * inv + b.x, 0.0f),
                                    fmaxf(acc.y * inv + b.y, 0.0f));
    __half2 o23 = __floats2half2_rn(fmaxf(acc.z * inv + b.z, 0.0f),
                                    fmaxf(acc.w * inv + b.w, 0.0f));
    uint2 ov;
    ov.x = *(unsigned*)&o01;
    ov.y = *(unsigned*)&o23;
    *(uint2*)&g_hreluh[n * 128 + lane * 4] = ov;
}

// ---------------- GEMM2 (+ fused a_src2/a_dst2): h2 = hrelu @ W2 -------------
__global__ __launch_bounds__(256) void gemm2_kernel(const float* __restrict__ W2,
                                                    const float* __restrict__ att_s,
                                                    const float* __restrict__ att_d) {
    __shared__ float Ws[128 * 16];
    __shared__ float Hs[16][128];
    int tid = threadIdx.x;
    int base = blockIdx.x * 16;
    for (int i = tid; i < 128 * 16; i += 256) Ws[i] = W2[i];
    for (int i = tid; i < 16 * 128; i += 256) {
        int r = i >> 7, c = i & 127;
        int gr = base + r;
        Hs[r][c] = (gr < N_NODES) ? __half2float(g_hreluh[gr * 128 + c]) : 0.0f;
    }
    __syncthreads();
    int ty = tid >> 4, tx = tid & 15;
    float sum = 0.0f;
#pragma unroll 8
    for (int k = 0; k < 128; k++) sum += Hs[ty][k] * Ws[k * 16 + tx];
    float ss = sum * att_s[tx];
    float sd = sum * att_d[tx];
#pragma unroll
    for (int off = 8; off; off >>= 1) {
        ss += __shfl_xor_sync(0xffffffffu, ss, off);
        sd += __shfl_xor_sync(0xffffffffu, sd, off);
    }
    int row = base + ty;
    if (row < N_NODES) {
        g_h2h[row * 16 + tx] = __float2half_rn(sum);
        if (tx == 0) { g_asrc2[row] = ss; g_adst2[row] = sd; }
    }
}

// ---------------- layer2 gather: 4 lanes per node, 8-edge index batching -----
__global__ __launch_bounds__(256) void gather2_kernel(const float* __restrict__ bias,
                                                      float* __restrict__ out) {
    int gid = blockIdx.x * blockDim.x + threadIdx.x;
    int n = gid >> 2;
    int q = gid & 3;
    if (n >= N_NODES) return;
    float adv = g_adst2[n];
    int j = g_off[n], jend = g_off[n + 1];
    float4 acc = make_float4(0.f, 0.f, 0.f, 0.f);
    float dsum = 0.0f;
    for (; j + 7 < jend; j += 8) {
        int s[8];
#pragma unroll
        for (int k = 0; k < 8; k++) s[k] = g_csr_src[j + k];
        float a[8];
#pragma unroll
        for (int k = 0; k < 8; k++) a[k] = g_asrc2[s[k]];
        uint2 r[8];
#pragma unroll
        for (int k = 0; k < 8; k++) r[k] = *(const uint2*)&g_h2h[s[k] * 16 + q * 4];
#pragma unroll
        for (int k = 0; k < 8; k++) {
            float e = __expf(lrelu(a[k] + adv));
            facc4(acc, r[k], e);
            dsum += e;
        }
    }
    for (; j < jend; j++) {
        int sa = g_csr_src[j];
        float ea = __expf(lrelu(g_asrc2[sa] + adv));
        uint2 rw = *(const uint2*)&g_h2h[sa * 16 + q * 4];
        facc4(acc, rw, ea);
        dsum += ea;
    }
    float inv = 1.0f / dsum;
    float4 b = *(const float4*)&bias[q * 4];
    float4 v;
    v.x = acc.x * inv + b.x;
    v.y = acc.y * inv + b.y;
    v.z = acc.z * inv + b.z;
    v.w = acc.w * inv + b.w;
    *(float4*)&out[n * 16 + q * 4] = v;
}

// ---------------- launch: fork CSR chain || gemm1, join before gather1 -------
extern "C" void kernel_launch(void* const* d_in, const int* in_sizes, int n_in,
                              void* d_out, int out_size) {
    const float* x      = (const float*)d_in[0];
    const int*   ei     = (const int*)d_in[1];
    const float* W1     = (const float*)d_in[2];
    const float* att_s1 = (const float*)d_in[3];
    const float* att_d1 = (const float*)d_in[4];
    const float* b1     = (const float*)d_in[5];
    const float* W2     = (const float*)d_in[6];
    const float* att_s2 = (const float*)d_in[7];
    const float* att_d2 = (const float*)d_in[8];
    const float* b2     = (const float*)d_in[9];
    float* out = (float*)d_out;
    const int* src = ei;
    const int* dst = ei + N_EDGES;

    cudaStream_t s2;
    cudaEvent_t evFork, evJoin;
    cudaStreamCreateWithFlags(&s2, cudaStreamNonBlocking);
    cudaEventCreateWithFlags(&evFork, cudaEventDisableTiming);
    cudaEventCreateWithFlags(&evJoin, cudaEventDisableTiming);

    // fork
    cudaEventRecord(evFork, 0);
    cudaStreamWaitEvent(s2, evFork, 0);

    // chain A (CSR build) on s2
    count_kernel<<<(E_TOT + 255) / 256, 256, 0, s2>>>(dst);
    scanA_kernel<<<NBLK_SCAN, 256, 0, s2>>>();
    scanC_kernel<<<NBLK_SCAN, 256, 0, s2>>>();
    scatter_kernel<<<(E_TOT + 255) / 256, 256, 0, s2>>>(src, dst);
    cudaEventRecord(evJoin, s2);

    // chain B (gemm1) on stream 0, concurrent with chain A
    dim3 g1grid((N_NODES + 127) / 128, 2);
    gemm1_kernel<<<g1grid, 256>>>(x, W1, att_s1, att_d1);

    // join: gather1 needs both CSR and h1/att scores
    cudaStreamWaitEvent(0, evJoin, 0);
    gather1_kernel<<<(N_NODES * 32 + 255) / 256, 256>>>(b1);
    gemm2_kernel<<<(N_NODES + 15) / 16, 256>>>(W2, att_s2, att_d2);
    gather2_kernel<<<(N_NODES * 4 + 255) / 256, 256>>>(b2, out);
}